// round 9
// baseline (speedup 1.0000x reference)
#include <cuda_runtime.h>
#include <cuda_bf16.h>
#include <cuda_fp16.h>
#include <math.h>
#include <utility>
#include <cstdint>

#define BATCH 32
#define D 256
#define CIN 2048
#define M 784
#define NNS 8
#define NPOW 10

typedef unsigned long long ull;
typedef unsigned int u32;

// ---------------- scratch (device globals) ---------------------------------
__device__ float g_Z[BATCH * D * M];        // conv acts fp32; later X (expm)
__device__ __half g_Zh[BATCH * D * M];      // BN+ReLU activations fp16
__device__ float g_cov[BATCH * D * D];
__device__ float g_Y[BATCH * D * D];
__device__ float g_Y2[BATCH * D * D];
__device__ float g_Zm[BATCH * D * D];
__device__ float g_Z2[BATCH * D * D];
__device__ float g_T[BATCH * D * D];
__device__ float g_E[BATCH * D * D];
__device__ float g_E2[BATCH * D * D];
__device__ float g_bnsum[D];
__device__ float g_bnsq[D];
__device__ float g_rmean[BATCH * D];
__device__ float g_tau[BATCH];
__device__ float g_stau[BATCH];
__device__ float g_nrm[BATCH];

// ---------------- helpers ---------------------------------------------------
__device__ __forceinline__ u32 smem_u32(const void* p) {
    u32 a;
    asm("{ .reg .u64 t; cvta.to.shared.u64 t, %1; cvt.u32.u64 %0, t; }" : "=r"(a) : "l"(p));
    return a;
}
__device__ __forceinline__ u32 pack2(float a, float b) {
    __nv_bfloat162 h = __floats2bfloat162_rn(a, b);
    return *reinterpret_cast<u32*>(&h);
}
__device__ __forceinline__ u32 pack2h(float a, float b) {
    __half2 h = __floats2half2_rn(a, b);
    return *reinterpret_cast<u32*>(&h);
}
__device__ __forceinline__ float lo_res(float a) {
    return a - __bfloat162float(__float2bfloat16_rn(a));
}
__device__ __forceinline__ void ldsm4(u32* r, u32 addr) {
    asm volatile("ldmatrix.sync.aligned.m8n8.x4.shared.b16 {%0,%1,%2,%3}, [%4];"
                 : "=r"(r[0]), "=r"(r[1]), "=r"(r[2]), "=r"(r[3]) : "r"(addr));
}
__device__ __forceinline__ void mma_bf16(float* d, const u32* a, const u32* b) {
    asm volatile(
        "mma.sync.aligned.m16n8k16.row.col.f32.bf16.bf16.f32 "
        "{%0,%1,%2,%3}, {%4,%5,%6,%7}, {%8,%9}, {%0,%1,%2,%3};"
        : "+f"(d[0]), "+f"(d[1]), "+f"(d[2]), "+f"(d[3])
        : "r"(a[0]), "r"(a[1]), "r"(a[2]), "r"(a[3]), "r"(b[0]), "r"(b[1]));
}
__device__ __forceinline__ void mma_fp16(float* d, const u32* a, const u32* b) {
    asm volatile(
        "mma.sync.aligned.m16n8k16.row.col.f32.f16.f16.f32 "
        "{%0,%1,%2,%3}, {%4,%5,%6,%7}, {%8,%9}, {%0,%1,%2,%3};"
        : "+f"(d[0]), "+f"(d[1]), "+f"(d[2]), "+f"(d[3])
        : "r"(a[0]), "r"(a[1]), "r"(a[2]), "r"(a[3]), "r"(b[0]), "r"(b[1]));
}

// ===========================================================================
// HMMA multi-op GEMM. CTA tile 128x64, 8 warps (4x2), warp tile 32x32,
// K chunks of 64, register-prefetch pipeline.
// Precision: default bf16 hi/lo split (3 mma); flag 8 = single fp16 mma.
// flags: 1 = B global is [K,N] (transposed smem fill; conv)
//        2 = NSFIRST epilogue  4 = COV epilogue
//        8 = fp16 single-MMA   16 = BN-stats accumulation epilogue
// ===========================================================================
struct OpDesc {
    const float* A; const float* B; float* C; const float* aux; const float* alphaDev;
    long long sA, sB, sC;
    float alpha, gamma;
    int K, lda, ldb, ldc, Ndim, flags;
};

#define A_TILE (128 * 144)
#define B_TILE (64 * 144)
#define OFF_AH 0
#define OFF_AL A_TILE
#define OFF_BH (2 * A_TILE)
#define OFF_BL (2 * A_TILE + B_TILE)
#define SMEM_BYTES (2 * A_TILE + 2 * B_TILE)

__global__ void __launch_bounds__(256, 2)
tc_gemm(OpDesc o0, OpDesc o1, OpDesc o2) {
    extern __shared__ char smem[];
    const int zz  = blockIdx.z;
    const int opi = zz >> 5;
    const OpDesc& o = (opi == 0) ? o0 : ((opi == 1) ? o1 : o2);
    const int b    = zz & 31;
    const int t    = threadIdx.x;
    const int wid  = t >> 5;
    const int lane = t & 31;
    const int n0   = blockIdx.x * 64;
    const int m0   = blockIdx.y * 128;

    const u32 sb = smem_u32(smem);
    const bool trans = (o.flags & 1);
    const bool fp16m = (o.flags & 8);

    const float* Ab = nullptr; const __half* AbH = nullptr;
    const float* Bb = nullptr; const __half* BbH = nullptr;
    if (fp16m && !trans) {
        AbH = (const __half*)o.A + (long long)b * o.sA;
        BbH = (const __half*)o.B + (long long)b * o.sB;
    } else {
        Ab = o.A + (long long)b * o.sA;
        Bb = o.B + (long long)b * o.sB;
    }

    float acc[2][4][4];
#pragma unroll
    for (int i = 0; i < 2; ++i)
#pragma unroll
        for (int j = 0; j < 4; ++j)
#pragma unroll
            for (int k = 0; k < 4; ++k) acc[i][j][k] = 0.f;

    const int wm = wid >> 1;
    const int wn = wid & 1;

    const int lAr = (lane & 7) + ((lane >> 3) & 1) * 8;
    const u32 lAc = ((lane >> 4) & 1) * 16;
    const int lBr = (lane & 7) + ((lane >> 4) & 1) * 8;
    const u32 lBc = ((lane >> 3) & 1) * 16;

    const int rgA  = t >> 4;
    const int kq4  = (t & 15) << 2;
    const int cN   = t & 63;
    const int cK0  = (t >> 6) << 4;
    const bool cOK = (n0 + cN) < o.Ndim;

    float4 pfA[8];
    float4 pfB4[4];
    float* pfBs = (float*)pfB4;

    const int nc = (o.K + 63) >> 6;

    auto prefetch = [&](int c) {
        const int kb = c << 6;
        const int kc = min(64, o.K - kb);
        if (kq4 < kc) {
            if (fp16m && !trans) {
#pragma unroll
                for (int i = 0; i < 8; ++i) {
                    uint2 v = *(const uint2*)(AbH + (size_t)(m0 + rgA + i * 16) * o.lda + kb + kq4);
                    pfA[i].x = __uint_as_float(v.x); pfA[i].y = __uint_as_float(v.y);
                }
#pragma unroll
                for (int i = 0; i < 4; ++i) {
                    uint2 v = *(const uint2*)(BbH + (size_t)(n0 + rgA + i * 16) * o.ldb + kb + kq4);
                    pfB4[i].x = __uint_as_float(v.x); pfB4[i].y = __uint_as_float(v.y);
                }
            } else {
#pragma unroll
                for (int i = 0; i < 8; ++i)
                    pfA[i] = *(const float4*)(Ab + (size_t)(m0 + rgA + i * 16) * o.lda + kb + kq4);
                if (!trans) {
#pragma unroll
                    for (int i = 0; i < 4; ++i)
                        pfB4[i] = *(const float4*)(Bb + (size_t)(n0 + rgA + i * 16) * o.ldb + kb + kq4);
                }
            }
        }
        if (trans) {
            const float* Bp = Bb + (size_t)(kb + cK0) * o.ldb + n0 + cN;
#pragma unroll
            for (int j = 0; j < 16; ++j)
                pfBs[j] = cOK ? Bp[(size_t)j * o.ldb] : 0.f;
        }
    };

    prefetch(0);

    for (int c = 0; c < nc; ++c) {
        const int kb = c << 6;
        const int kc = min(64, o.K - kb);
        __syncthreads();
        // ---- store prefetched chunk ----
        if (kq4 < kc) {
#pragma unroll
            for (int i = 0; i < 8; ++i) {
                const u32 off = (u32)((rgA + i * 16) * 144 + kq4 * 2);
                float4 v = pfA[i];
                if (!fp16m) {
                    *(uint2*)(smem + OFF_AH + off) = make_uint2(pack2(v.x, v.y), pack2(v.z, v.w));
                    *(uint2*)(smem + OFF_AL + off) =
                        make_uint2(pack2(lo_res(v.x), lo_res(v.y)), pack2(lo_res(v.z), lo_res(v.w)));
                } else if (trans) {
                    *(uint2*)(smem + OFF_AH + off) = make_uint2(pack2h(v.x, v.y), pack2h(v.z, v.w));
                } else {
                    *(uint2*)(smem + OFF_AH + off) =
                        make_uint2(__float_as_uint(v.x), __float_as_uint(v.y));
                }
            }
            if (!trans) {
#pragma unroll
                for (int i = 0; i < 4; ++i) {
                    const u32 off = (u32)((rgA + i * 16) * 144 + kq4 * 2);
                    float4 v = pfB4[i];
                    if (!fp16m) {
                        *(uint2*)(smem + OFF_BH + off) = make_uint2(pack2(v.x, v.y), pack2(v.z, v.w));
                        *(uint2*)(smem + OFF_BL + off) =
                            make_uint2(pack2(lo_res(v.x), lo_res(v.y)), pack2(lo_res(v.z), lo_res(v.w)));
                    } else {
                        *(uint2*)(smem + OFF_BH + off) =
                            make_uint2(__float_as_uint(v.x), __float_as_uint(v.y));
                    }
                }
            }
        }
        if (trans) {
#pragma unroll
            for (int j = 0; j < 4; ++j) {
                const u32 off = (u32)(cN * 144 + (cK0 + j * 4) * 2);
                float v0 = pfBs[j * 4], v1 = pfBs[j * 4 + 1];
                float v2 = pfBs[j * 4 + 2], v3 = pfBs[j * 4 + 3];
                if (!fp16m) {
                    *(uint2*)(smem + OFF_BH + off) = make_uint2(pack2(v0, v1), pack2(v2, v3));
                    *(uint2*)(smem + OFF_BL + off) =
                        make_uint2(pack2(lo_res(v0), lo_res(v1)), pack2(lo_res(v2), lo_res(v3)));
                } else {
                    *(uint2*)(smem + OFF_BH + off) = make_uint2(pack2h(v0, v1), pack2h(v2, v3));
                }
            }
        }
        __syncthreads();
        if (c + 1 < nc) prefetch(c + 1);
        // ---- compute ----
        const int ns = kc >> 4;
        if (fp16m) {
            for (int ks = 0; ks < ns; ++ks) {
                const u32 kbyte = (u32)(ks * 32);
                u32 bh[2][4];
#pragma unroll
                for (int pr = 0; pr < 2; ++pr)
                    ldsm4(bh[pr], sb + (u32)((wn * 32 + pr * 16 + lBr) * 144) + kbyte + lBc + OFF_BH);
#pragma unroll
                for (int mf = 0; mf < 2; ++mf) {
                    u32 ah[4];
                    ldsm4(ah, sb + (u32)((wm * 32 + mf * 16 + lAr) * 144) + kbyte + lAc + OFF_AH);
#pragma unroll
                    for (int nf = 0; nf < 4; ++nf)
                        mma_fp16(acc[mf][nf], ah, &bh[nf >> 1][(nf & 1) * 2]);
                }
            }
        } else {
            for (int ks = 0; ks < ns; ++ks) {
                const u32 kbyte = (u32)(ks * 32);
                u32 bh[2][4], bl[2][4];
#pragma unroll
                for (int pr = 0; pr < 2; ++pr) {
                    const u32 ba = sb + (u32)((wn * 32 + pr * 16 + lBr) * 144) + kbyte + lBc;
                    ldsm4(bh[pr], ba + OFF_BH);
                    ldsm4(bl[pr], ba + OFF_BL);
                }
#pragma unroll
                for (int mf = 0; mf < 2; ++mf) {
                    u32 ah[4], al[4];
                    const u32 aa = sb + (u32)((wm * 32 + mf * 16 + lAr) * 144) + kbyte + lAc;
                    ldsm4(ah, aa + OFF_AH);
                    ldsm4(al, aa + OFF_AL);
#pragma unroll
                    for (int nf = 0; nf < 4; ++nf) {
                        const u32* bhf = &bh[nf >> 1][(nf & 1) * 2];
                        const u32* blf = &bl[nf >> 1][(nf & 1) * 2];
                        mma_bf16(acc[mf][nf], ah, bhf);
                        mma_bf16(acc[mf][nf], ah, blf);
                        mma_bf16(acc[mf][nf], al, bhf);
                    }
                }
            }
        }
    }

    // ---------------- epilogue ----------------
    const float aeff = o.alpha * (o.alphaDev ? o.alphaDev[b] : 1.f);
    float* Cb = o.C + (long long)b * o.sC;
    const int mb = m0 + wm * 32 + (lane >> 2);
    const int cb = n0 + wn * 32 + (lane & 3) * 2;

    float zs[4] = {0.f, 0.f, 0.f, 0.f}, zq[4] = {0.f, 0.f, 0.f, 0.f};

#pragma unroll
    for (int mf = 0; mf < 2; ++mf) {
#pragma unroll
        for (int nf = 0; nf < 4; ++nf) {
            const int c  = cb + nf * 8;
            const int r1 = mb + mf * 16;
            const int r2 = r1 + 8;
            float d0 = acc[mf][nf][0], d1 = acc[mf][nf][1];
            float d2 = acc[mf][nf][2], d3 = acc[mf][nf][3];

            if (o.flags & 4) {
                const float* rm = o.aux + b * D;
                const float invM = 1.f / (float)M;
                const float rc0 = rm[c], rc1 = rm[c + 1];
                *(float2*)&Cb[(size_t)r1 * o.ldc + c] =
                    make_float2(d0 * invM - rm[r1] * rc0, d1 * invM - rm[r1] * rc1);
                *(float2*)&Cb[(size_t)r2 * o.ldc + c] =
                    make_float2(d2 * invM - rm[r2] * rc0, d3 * invM - rm[r2] * rc1);
            } else if (o.flags & 2) {
                float* C2b = (float*)o.aux + (long long)b * (long long)(D * D);
                float2 a1 = *(const float2*)&Ab[(size_t)r1 * o.lda + c];
                float2 a2 = *(const float2*)&Ab[(size_t)r2 * o.lda + c];
                *(float2*)&Cb[(size_t)r1 * o.ldc + c] =
                    make_float2(1.5f * a1.x - 0.5f * d0, 1.5f * a1.y - 0.5f * d1);
                *(float2*)&Cb[(size_t)r2 * o.ldc + c] =
                    make_float2(1.5f * a2.x - 0.5f * d2, 1.5f * a2.y - 0.5f * d3);
                float2 z1 = make_float2(-0.5f * a1.x, -0.5f * a1.y);
                float2 z2 = make_float2(-0.5f * a2.x, -0.5f * a2.y);
                if (r1 == c)     z1.x += 1.5f;
                if (r1 == c + 1) z1.y += 1.5f;
                if (r2 == c)     z2.x += 1.5f;
                if (r2 == c + 1) z2.y += 1.5f;
                *(float2*)&C2b[(size_t)r1 * o.ldc + c] = z1;
                *(float2*)&C2b[(size_t)r2 * o.ldc + c] = z2;
            } else {
                if (c >= o.Ndim) continue;
                float2 v1 = make_float2(aeff * d0, aeff * d1);
                float2 v2 = make_float2(aeff * d2, aeff * d3);
                if (o.gamma != 0.f) {
                    if (r1 == c)     v1.x += o.gamma;
                    if (r1 == c + 1) v1.y += o.gamma;
                    if (r2 == c)     v2.x += o.gamma;
                    if (r2 == c + 1) v2.y += o.gamma;
                }
                *(float2*)&Cb[(size_t)r1 * o.ldc + c] = v1;
                *(float2*)&Cb[(size_t)r2 * o.ldc + c] = v2;
                if (o.flags & 16) {
                    zs[mf * 2 + 0] += v1.x + v1.y;
                    zq[mf * 2 + 0] += v1.x * v1.x + v1.y * v1.y;
                    zs[mf * 2 + 1] += v2.x + v2.y;
                    zq[mf * 2 + 1] += v2.x * v2.x + v2.y * v2.y;
                }
            }
        }
    }

    if (o.flags & 16) {
        __syncthreads();
        float* sred = (float*)smem;     // 256 floats: [0:128) sums, [128:256) sumsq
        if (t < 128) { sred[t] = 0.f; sred[128 + t] = 0.f; }
        __syncthreads();
#pragma unroll
        for (int q = 0; q < 4; ++q) {
            const int lr = wm * 32 + (lane >> 2) + (q >> 1) * 16 + (q & 1) * 8;
            atomicAdd(&sred[lr], zs[q]);
            atomicAdd(&sred[128 + lr], zq[q]);
        }
        __syncthreads();
        if (t < 128) {
            atomicAdd(&g_bnsum[m0 + t], sred[t]);
            atomicAdd(&g_bnsq[m0 + t], sred[128 + t]);
        }
    }
}

// ---------------- zero BN accumulators -------------------------------------
__global__ void zero_stats() {
    g_bnsum[threadIdx.x] = 0.f;
    g_bnsq[threadIdx.x] = 0.f;
}

// ---------------- BN apply + ReLU -> fp16, row mean ------------------------
__global__ void bn_apply(const float* __restrict__ Z,
                         const float* __restrict__ gamma, const float* __restrict__ beta,
                         __half* __restrict__ Zh, float* __restrict__ rmean) {
    const int bd = blockIdx.x;
    const int d = bd & (D - 1);
    const float Ninv = 1.f / (float)(BATCH * M);
    const float mu = g_bnsum[d] * Ninv;
    const float var = g_bnsq[d] * Ninv - mu * mu;
    const float sc = rsqrtf(var + 1e-5f) * gamma[d];
    const float sh = beta[d] - mu * sc;
    const float* row = Z + (size_t)bd * M;
    __half* oh = Zh + (size_t)bd * M;
    float s = 0.f;
    for (int i = threadIdx.x; i < M; i += blockDim.x) {
        float v = fmaxf(row[i] * sc + sh, 0.f);
        oh[i] = __float2half(v);
        s += v;
    }
    __shared__ float sm[128];
    sm[threadIdx.x] = s;
    __syncthreads();
    for (int o = 64; o > 0; o >>= 1) {
        if (threadIdx.x < o) sm[threadIdx.x] += sm[threadIdx.x + o];
        __syncthreads();
    }
    if (threadIdx.x == 0) rmean[bd] = sm[0] * (1.f / (float)M);
}

// ---------------- power iteration; tau = lambda_max/2 ----------------------
__global__ void power_iter(const float* __restrict__ cov, float* __restrict__ tau,
                           float* __restrict__ stau) {
    const int b = blockIdx.x;
    const float* Cb = cov + (size_t)b * D * D;
    __shared__ float v[D];
    __shared__ float red[256];
    const int t = threadIdx.x;
    v[t] = 1.f;
    __syncthreads();
    float lam = 1.f;
    for (int it = 0; it < NPOW; ++it) {
        float w = 0.f;
#pragma unroll 8
        for (int j = 0; j < D; ++j) w = fmaf(Cb[(size_t)j * D + t], v[j], w);
        red[t] = w * w;
        __syncthreads();
        for (int o = 128; o > 0; o >>= 1) {
            if (t < o) red[t] += red[t + o];
            __syncthreads();
        }
        lam = sqrtf(red[0]);
        v[t] = w / fmaxf(lam, 1e-20f);
        __syncthreads();
    }
    if (t == 0) {
        float l = fmaxf(lam, 1e-12f) * 0.5f;
        tau[b] = l;
        stau[b] = sqrtf(l);
    }
}

// ---------------- fused init: Anorm, X, E ----------------------------------
__global__ void init_mats(const float* __restrict__ cov, const float* __restrict__ tau,
                          float* __restrict__ An, float* __restrict__ X,
                          float* __restrict__ E) {
    const int b = blockIdx.y, i = blockIdx.x;
    const float it = 1.f / tau[b];
    const size_t off = ((size_t)b * D + i) * D;
    for (int j = threadIdx.x; j < D; j += blockDim.x) {
        float c = cov[off + j];
        An[off + j] = c * it;
        float x = c * (-1.f / 64.f);
        X[off + j] = x;
        E[off + j] = 0.2f * x + ((i == j) ? 1.f : 0.f);
    }
}

// ---------------- Frobenius norm per batch ---------------------------------
__global__ void frob_norm(const float* __restrict__ A, float* __restrict__ out) {
    const int b = blockIdx.x;
    const float* Ab = A + (size_t)b * D * D;
    float ss = 0.f;
    for (int i = threadIdx.x; i < D * D; i += 256) {
        float v = Ab[i];
        ss += v * v;
    }
    __shared__ float sm[256];
    sm[threadIdx.x] = ss;
    __syncthreads();
    for (int o = 128; o > 0; o >>= 1) {
        if (threadIdx.x < o) sm[threadIdx.x] += sm[threadIdx.x + o];
        __syncthreads();
    }
    if (threadIdx.x == 0) out[b] = fmaxf(sqrtf(sm[0]), 1e-12f);
}

__global__ void out_triu(const float* __restrict__ Sq, const float* __restrict__ nrm,
                         float* __restrict__ out) {
    const int b = blockIdx.y, i = blockIdx.x;
    const float sc = 1.f + nrm[b];
    const size_t rowoff = (size_t)i * D - (size_t)i * (i - 1) / 2;
    const float* row = Sq + ((size_t)b * D + i) * D;
    float* ob = out + (size_t)b * (D * (D + 1) / 2) + rowoff - i;
    for (int j = i + (int)threadIdx.x; j < D; j += blockDim.x) ob[j] = sc * row[j];
}

// ---------------------------------------------------------------------------
static float* sym_addr(const void* symbol) {
    void* p = nullptr;
    cudaGetSymbolAddress(&p, symbol);
    return (float*)p;
}

static OpDesc mkop(const float* A, const float* B, float* C, float alpha,
                   float gamma, int K, int lda, int ldb, int ldc, int Ndim, int flags,
                   const float* aux = nullptr, const float* alphaDev = nullptr,
                   long long sA = (long long)D * D, long long sB = (long long)D * D,
                   long long sC = (long long)D * D) {
    OpDesc o;
    o.A = A; o.B = B; o.C = C; o.aux = aux; o.alphaDev = alphaDev;
    o.sA = sA; o.sB = sB; o.sC = sC;
    o.alpha = alpha; o.gamma = gamma;
    o.K = K; o.lda = lda; o.ldb = ldb; o.ldc = ldc; o.Ndim = Ndim; o.flags = flags;
    return o;
}

extern "C" void kernel_launch(void* const* d_in, const int* in_sizes, int n_in,
                              void* d_out, int out_size) {
    const float* x  = (const float*)d_in[0];
    const float* w  = (const float*)d_in[1];
    const float* gm = (const float*)d_in[2];
    const float* bt = (const float*)d_in[3];
    float* out = (float*)d_out;

    float* Z    = sym_addr(g_Z);
    float* Zh   = sym_addr(g_Zh);     // __half*, cast where needed
    float* cov  = sym_addr(g_cov);
    float* Y    = sym_addr(g_Y);
    float* Y2   = sym_addr(g_Y2);
    float* Zm   = sym_addr(g_Zm);
    float* Z2   = sym_addr(g_Z2);
    float* T    = sym_addr(g_T);
    float* E    = sym_addr(g_E);
    float* E2   = sym_addr(g_E2);
    float* rmn  = sym_addr(g_rmean);
    float* tau  = sym_addr(g_tau);
    float* stau = sym_addr(g_stau);
    float* nrm  = sym_addr(g_nrm);

    cudaFuncSetAttribute(tc_gemm, cudaFuncAttributeMaxDynamicSharedMemorySize, SMEM_BYTES);

    // expm op sequencer: 4 Taylor (k=4..1) + 6 squarings
    float* Xb = Z;          // X = -cov/64 reuses g_Z after activations retire
    float* Ec = E; float* En = E2;
    int expmStage = 0;
    auto nextExpmOp = [&](OpDesc* slot) -> bool {
        if (expmStage >= 10) return false;
        if (expmStage < 4) {
            float kinv = 1.f / (float)(4 - expmStage);
            *slot = mkop(Xb, Ec, En, kinv, 1.f, D, D, D, D, D, 0);
        } else {
            *slot = mkop(Ec, Ec, En, 1.f, 0.f, D, D, D, D, D, 0);
        }
        std::swap(Ec, En);
        ++expmStage;
        return true;
    };

    OpDesc dummy = mkop(cov, cov, T, 0.f, 0.f, D, D, D, D, D, 0);

    auto launch = [&](OpDesc* ops, int n) {
        tc_gemm<<<dim3(4, 2, 32 * n), 256, SMEM_BYTES>>>(ops[0], n > 1 ? ops[1] : dummy,
                                                         n > 2 ? ops[2] : dummy);
    };

    // 0. zero BN stat accumulators
    zero_stats<<<1, D>>>();
    // 1. conv 1x1 (fp16 single-MMA) with fused BN-stat accumulation
    {
        OpDesc c = mkop(w, x, Z, 1.f, 0.f, CIN, CIN, M, M, M, 1 | 8 | 16,
                        nullptr, nullptr, 0LL, (long long)CIN * M, (long long)D * M);
        tc_gemm<<<dim3(13, 2, 32), 256, SMEM_BYTES>>>(c, dummy, dummy);
    }
    // 2. BN apply + ReLU -> fp16 Zh + rmean
    bn_apply<<<BATCH * D, 128>>>(Z, gm, bt, (__half*)Zh, rmn);
    // 3. covariance (fp16 single-MMA): cov = Zh Zh^T / M - rmean rmean^T
    {
        OpDesc c = mkop(Zh, Zh, cov, 1.f, 0.f, M, M, M, D, D, 8 | 4,
                        rmn, nullptr, (long long)D * M, (long long)D * M, (long long)D * D);
        launch(&c, 1);
    }
    // 4. spectral norm -> tau = lam/2
    power_iter<<<BATCH, 256>>>(cov, tau, stau);
    // 5. fused inits (Anorm->Y, X->g_Z, E)
    init_mats<<<dim3(D, BATCH), 256>>>(cov, tau, Y, Xb, E);

    // 6. round 1: NSFIRST (S=A^2 -> Y1,Z1) + expm rider
    {
        OpDesc ops[3]; int n = 0;
        ops[n++] = mkop(Y, Y, Y2, 1.f, 0.f, D, D, D, D, D, 2, Zm);
        if (nextExpmOp(&ops[n])) ++n;
        launch(ops, n);
    }
    float *Yc = Y2, *Zc = Zm, *Yn = Y, *Zn = Z2;
    float* Sq = nullptr;

    // 7. NS iterations 2..NNS with expm riders
    for (int it = 2; it <= NNS; ++it) {
        {   // round A: T = 3I - Z@Y (+ rider)
            OpDesc ops[3]; int n = 0;
            ops[n++] = mkop(Zc, Yc, T, -1.f, 3.f, D, D, D, D, D, 0);
            if (nextExpmOp(&ops[n])) ++n;
            launch(ops, n);
        }
        {   // round B (+ rider)
            OpDesc ops[3]; int n = 0;
            if (it < NNS) {
                ops[n++] = mkop(Yc, T, Yn, 0.5f, 0.f, D, D, D, D, D, 0);
                ops[n++] = mkop(T, Zc, Zn, 0.5f, 0.f, D, D, D, D, D, 0);
            } else {
                ops[n++] = mkop(Yc, T, Yn, 0.5f, 0.f, D, D, D, D, D, 0, nullptr, stau);
                Sq = Yn;
            }
            if (n < 3 && nextExpmOp(&ops[n])) ++n;
            launch(ops, n);
            std::swap(Yc, Yn); std::swap(Zc, Zn);
        }
    }
    // safety drain
    while (expmStage < 10) {
        OpDesc ops[3]; int n = 0;
        nextExpmOp(&ops[n]); ++n;
        launch(ops, n);
    }

    // 8. P = Sq @ E -> T, nrm = ||P||_F
    {
        OpDesc p = mkop(Sq, Ec, T, 1.f, 0.f, D, D, D, D, D, 0);
        launch(&p, 1);
    }
    frob_norm<<<BATCH, 256>>>(T, nrm);
    // 9. output
    out_triu<<<dim3(D, BATCH), 256>>>(Sq, nrm, out);

    (void)in_sizes; (void)n_in; (void)out_size;
}

// round 10
// speedup vs baseline: 1.1861x; 1.1861x over previous
#include <cuda_runtime.h>
#include <cuda_bf16.h>
#include <cuda_fp16.h>
#include <math.h>
#include <cstdint>

#define BATCH 32
#define D 256
#define CIN 2048
#define M 784
#define NPOW 16

// scaled Newton-Schulz schedule (equioscillation, designed for lmin/lmax >= 0.004)
#define C1 2.79f
#define C2 2.52f
#define C3 1.98f
#define C4 1.35f
#define C5 1.045f
#define C6 1.0005f
#define S1 1.670329f
#define S2 1.587451f
#define S3 1.407125f
#define S4 1.161895f
#define S5 1.022252f
#define S6 1.000250f

typedef unsigned int u32;

// ---------------- scratch (device globals) ---------------------------------
__device__ float g_Z[BATCH * D * M];        // conv acts fp32; later X = -cov/64
__device__ __half g_Zh[BATCH * D * M];      // BN+ReLU activations fp16
__device__ float g_cov[BATCH * D * D];
__device__ float g_Y[BATCH * D * D];        // Y0; final Sq
__device__ float g_Y2[BATCH * D * D];
__device__ float g_Zm[BATCH * D * D];
__device__ float g_Z2[BATCH * D * D];
__device__ float g_T[BATCH * D * D];        // T; final P
__device__ float g_E[BATCH * D * D];
__device__ float g_E2[BATCH * D * D];
__device__ float g_bnsum[D];
__device__ float g_bnsq[D];
__device__ float g_rmean[BATCH * D];
__device__ float g_tau[BATCH];
__device__ float g_stau[BATCH];
__device__ float g_nrm[BATCH];
__device__ unsigned g_bar;

// ---------------- helpers ---------------------------------------------------
__device__ __forceinline__ u32 smem_u32(const void* p) {
    u32 a;
    asm("{ .reg .u64 t; cvta.to.shared.u64 t, %1; cvt.u32.u64 %0, t; }" : "=r"(a) : "l"(p));
    return a;
}
__device__ __forceinline__ u32 pack2(float a, float b) {
    __nv_bfloat162 h = __floats2bfloat162_rn(a, b);
    return *reinterpret_cast<u32*>(&h);
}
__device__ __forceinline__ u32 pack2h(float a, float b) {
    __half2 h = __floats2half2_rn(a, b);
    return *reinterpret_cast<u32*>(&h);
}
__device__ __forceinline__ float lo_res(float a) {
    return a - __bfloat162float(__float2bfloat16_rn(a));
}
__device__ __forceinline__ void ldsm4(u32* r, u32 addr) {
    asm volatile("ldmatrix.sync.aligned.m8n8.x4.shared.b16 {%0,%1,%2,%3}, [%4];"
                 : "=r"(r[0]), "=r"(r[1]), "=r"(r[2]), "=r"(r[3]) : "r"(addr));
}
__device__ __forceinline__ void mma_bf16(float* d, const u32* a, const u32* b) {
    asm volatile(
        "mma.sync.aligned.m16n8k16.row.col.f32.bf16.bf16.f32 "
        "{%0,%1,%2,%3}, {%4,%5,%6,%7}, {%8,%9}, {%0,%1,%2,%3};"
        : "+f"(d[0]), "+f"(d[1]), "+f"(d[2]), "+f"(d[3])
        : "r"(a[0]), "r"(a[1]), "r"(a[2]), "r"(a[3]), "r"(b[0]), "r"(b[1]));
}
__device__ __forceinline__ void mma_fp16(float* d, const u32* a, const u32* b) {
    asm volatile(
        "mma.sync.aligned.m16n8k16.row.col.f32.f16.f16.f32 "
        "{%0,%1,%2,%3}, {%4,%5,%6,%7}, {%8,%9}, {%0,%1,%2,%3};"
        : "+f"(d[0]), "+f"(d[1]), "+f"(d[2]), "+f"(d[3])
        : "r"(a[0]), "r"(a[1]), "r"(a[2]), "r"(a[3]), "r"(b[0]), "r"(b[1]));
}

// ===========================================================================
// GEMM tile body. CTA tile 128x64, 8 warps (4x2), warp tile 32x32,
// K chunks of 64, register-prefetch pipeline.
// Precision: default bf16 hi/lo split (3 mma); flag 8 = single fp16 mma.
// flags: 1=trans B ([K,N] global), 4=COV epi, 8=fp16, 16=BN-stat accum
// General epilogue: C = alpha*(alphaDev?)*acc + beta*A + gamma*diag
// ===========================================================================
struct OpDesc {
    const float* A; const float* B; float* C; const float* aux; const float* alphaDev;
    long long sA, sB, sC;
    float alpha, beta, gamma;
    int K, lda, ldb, ldc, Ndim, flags;
};

#define A_TILE (128 * 144)
#define B_TILE (64 * 144)
#define OFF_AH 0
#define OFF_AL A_TILE
#define OFF_BH (2 * A_TILE)
#define OFF_BL (2 * A_TILE + B_TILE)
#define SMEM_BYTES (2 * A_TILE + 2 * B_TILE)

__device__ void gemm_tile(const OpDesc& o, const int b, const int m0, const int n0,
                          char* smem) {
    const int t    = threadIdx.x;
    const int wid  = t >> 5;
    const int lane = t & 31;
    const u32 sb = smem_u32(smem);
    const bool trans = (o.flags & 1);
    const bool fp16m = (o.flags & 8);

    const float* Ab = nullptr; const __half* AbH = nullptr;
    const float* Bb = nullptr; const __half* BbH = nullptr;
    if (fp16m && !trans) {
        AbH = (const __half*)o.A + (long long)b * o.sA;
        BbH = (const __half*)o.B + (long long)b * o.sB;
    } else {
        Ab = o.A + (long long)b * o.sA;
        Bb = o.B + (long long)b * o.sB;
    }

    float acc[2][4][4];
#pragma unroll
    for (int i = 0; i < 2; ++i)
#pragma unroll
        for (int j = 0; j < 4; ++j)
#pragma unroll
            for (int k = 0; k < 4; ++k) acc[i][j][k] = 0.f;

    const int wm = wid >> 1;
    const int wn = wid & 1;
    const int lAr = (lane & 7) + ((lane >> 3) & 1) * 8;
    const u32 lAc = ((lane >> 4) & 1) * 16;
    const int lBr = (lane & 7) + ((lane >> 4) & 1) * 8;
    const u32 lBc = ((lane >> 3) & 1) * 16;
    const int rgA  = t >> 4;
    const int kq4  = (t & 15) << 2;
    const int cN   = t & 63;
    const int cK0  = (t >> 6) << 4;
    const bool cOK = (n0 + cN) < o.Ndim;

    float4 pfA[8];
    float4 pfB4[4];
    float* pfBs = (float*)pfB4;
    const int nc = (o.K + 63) >> 6;

    auto prefetch = [&](int c) {
        const int kb = c << 6;
        const int kc = min(64, o.K - kb);
        if (kq4 < kc) {
            if (fp16m && !trans) {
#pragma unroll
                for (int i = 0; i < 8; ++i) {
                    uint2 v = *(const uint2*)(AbH + (size_t)(m0 + rgA + i * 16) * o.lda + kb + kq4);
                    pfA[i].x = __uint_as_float(v.x); pfA[i].y = __uint_as_float(v.y);
                }
#pragma unroll
                for (int i = 0; i < 4; ++i) {
                    uint2 v = *(const uint2*)(BbH + (size_t)(n0 + rgA + i * 16) * o.ldb + kb + kq4);
                    pfB4[i].x = __uint_as_float(v.x); pfB4[i].y = __uint_as_float(v.y);
                }
            } else {
#pragma unroll
                for (int i = 0; i < 8; ++i)
                    pfA[i] = *(const float4*)(Ab + (size_t)(m0 + rgA + i * 16) * o.lda + kb + kq4);
                if (!trans) {
#pragma unroll
                    for (int i = 0; i < 4; ++i)
                        pfB4[i] = *(const float4*)(Bb + (size_t)(n0 + rgA + i * 16) * o.ldb + kb + kq4);
                }
            }
        }
        if (trans) {
            const float* Bp = Bb + (size_t)(kb + cK0) * o.ldb + n0 + cN;
#pragma unroll
            for (int j = 0; j < 16; ++j)
                pfBs[j] = cOK ? Bp[(size_t)j * o.ldb] : 0.f;
        }
    };

    prefetch(0);

    for (int c = 0; c < nc; ++c) {
        const int kb = c << 6;
        const int kc = min(64, o.K - kb);
        __syncthreads();
        if (kq4 < kc) {
#pragma unroll
            for (int i = 0; i < 8; ++i) {
                const u32 off = (u32)((rgA + i * 16) * 144 + kq4 * 2);
                float4 v = pfA[i];
                if (!fp16m) {
                    *(uint2*)(smem + OFF_AH + off) = make_uint2(pack2(v.x, v.y), pack2(v.z, v.w));
                    *(uint2*)(smem + OFF_AL + off) =
                        make_uint2(pack2(lo_res(v.x), lo_res(v.y)), pack2(lo_res(v.z), lo_res(v.w)));
                } else if (trans) {
                    *(uint2*)(smem + OFF_AH + off) = make_uint2(pack2h(v.x, v.y), pack2h(v.z, v.w));
                } else {
                    *(uint2*)(smem + OFF_AH + off) =
                        make_uint2(__float_as_uint(v.x), __float_as_uint(v.y));
                }
            }
            if (!trans) {
#pragma unroll
                for (int i = 0; i < 4; ++i) {
                    const u32 off = (u32)((rgA + i * 16) * 144 + kq4 * 2);
                    float4 v = pfB4[i];
                    if (!fp16m) {
                        *(uint2*)(smem + OFF_BH + off) = make_uint2(pack2(v.x, v.y), pack2(v.z, v.w));
                        *(uint2*)(smem + OFF_BL + off) =
                            make_uint2(pack2(lo_res(v.x), lo_res(v.y)), pack2(lo_res(v.z), lo_res(v.w)));
                    } else {
                        *(uint2*)(smem + OFF_BH + off) =
                            make_uint2(__float_as_uint(v.x), __float_as_uint(v.y));
                    }
                }
            }
        }
        if (trans) {
#pragma unroll
            for (int j = 0; j < 4; ++j) {
                const u32 off = (u32)(cN * 144 + (cK0 + j * 4) * 2);
                float v0 = pfBs[j * 4], v1 = pfBs[j * 4 + 1];
                float v2 = pfBs[j * 4 + 2], v3 = pfBs[j * 4 + 3];
                if (!fp16m) {
                    *(uint2*)(smem + OFF_BH + off) = make_uint2(pack2(v0, v1), pack2(v2, v3));
                    *(uint2*)(smem + OFF_BL + off) =
                        make_uint2(pack2(lo_res(v0), lo_res(v1)), pack2(lo_res(v2), lo_res(v3)));
                } else {
                    *(uint2*)(smem + OFF_BH + off) = make_uint2(pack2h(v0, v1), pack2h(v2, v3));
                }
            }
        }
        __syncthreads();
        if (c + 1 < nc) prefetch(c + 1);

        const int ns = kc >> 4;
        if (fp16m) {
            for (int ks = 0; ks < ns; ++ks) {
                const u32 kbyte = (u32)(ks * 32);
                u32 bh[2][4];
#pragma unroll
                for (int pr = 0; pr < 2; ++pr)
                    ldsm4(bh[pr], sb + (u32)((wn * 32 + pr * 16 + lBr) * 144) + kbyte + lBc + OFF_BH);
#pragma unroll
                for (int mf = 0; mf < 2; ++mf) {
                    u32 ah[4];
                    ldsm4(ah, sb + (u32)((wm * 32 + mf * 16 + lAr) * 144) + kbyte + lAc + OFF_AH);
#pragma unroll
                    for (int nf = 0; nf < 4; ++nf)
                        mma_fp16(acc[mf][nf], ah, &bh[nf >> 1][(nf & 1) * 2]);
                }
            }
        } else {
            for (int ks = 0; ks < ns; ++ks) {
                const u32 kbyte = (u32)(ks * 32);
                u32 bh[2][4], bl[2][4];
#pragma unroll
                for (int pr = 0; pr < 2; ++pr) {
                    const u32 ba = sb + (u32)((wn * 32 + pr * 16 + lBr) * 144) + kbyte + lBc;
                    ldsm4(bh[pr], ba + OFF_BH);
                    ldsm4(bl[pr], ba + OFF_BL);
                }
#pragma unroll
                for (int mf = 0; mf < 2; ++mf) {
                    u32 ah[4], al[4];
                    const u32 aa = sb + (u32)((wm * 32 + mf * 16 + lAr) * 144) + kbyte + lAc;
                    ldsm4(ah, aa + OFF_AH);
                    ldsm4(al, aa + OFF_AL);
#pragma unroll
                    for (int nf = 0; nf < 4; ++nf) {
                        const u32* bhf = &bh[nf >> 1][(nf & 1) * 2];
                        const u32* blf = &bl[nf >> 1][(nf & 1) * 2];
                        mma_bf16(acc[mf][nf], ah, bhf);
                        mma_bf16(acc[mf][nf], ah, blf);
                        mma_bf16(acc[mf][nf], al, bhf);
                    }
                }
            }
        }
    }

    // ---------------- epilogue ----------------
    const float aeff = o.alpha * (o.alphaDev ? o.alphaDev[b] : 1.f);
    float* Cb = o.C + (long long)b * o.sC;
    const int mb = m0 + wm * 32 + (lane >> 2);
    const int cb = n0 + wn * 32 + (lane & 3) * 2;

    float zs[4] = {0.f, 0.f, 0.f, 0.f}, zq[4] = {0.f, 0.f, 0.f, 0.f};

#pragma unroll
    for (int mf = 0; mf < 2; ++mf) {
#pragma unroll
        for (int nf = 0; nf < 4; ++nf) {
            const int c  = cb + nf * 8;
            const int r1 = mb + mf * 16;
            const int r2 = r1 + 8;
            float d0 = acc[mf][nf][0], d1 = acc[mf][nf][1];
            float d2 = acc[mf][nf][2], d3 = acc[mf][nf][3];

            if (o.flags & 4) {
                const float* rm = o.aux + b * D;
                const float invM = 1.f / (float)M;
                const float rc0 = rm[c], rc1 = rm[c + 1];
                *(float2*)&Cb[(size_t)r1 * o.ldc + c] =
                    make_float2(d0 * invM - rm[r1] * rc0, d1 * invM - rm[r1] * rc1);
                *(float2*)&Cb[(size_t)r2 * o.ldc + c] =
                    make_float2(d2 * invM - rm[r2] * rc0, d3 * invM - rm[r2] * rc1);
            } else {
                if (c >= o.Ndim) continue;
                float2 v1 = make_float2(aeff * d0, aeff * d1);
                float2 v2 = make_float2(aeff * d2, aeff * d3);
                if (o.beta != 0.f) {
                    float2 a1 = *(const float2*)&Ab[(size_t)r1 * o.lda + c];
                    float2 a2 = *(const float2*)&Ab[(size_t)r2 * o.lda + c];
                    v1.x += o.beta * a1.x; v1.y += o.beta * a1.y;
                    v2.x += o.beta * a2.x; v2.y += o.beta * a2.y;
                }
                if (o.gamma != 0.f) {
                    if (r1 == c)     v1.x += o.gamma;
                    if (r1 == c + 1) v1.y += o.gamma;
                    if (r2 == c)     v2.x += o.gamma;
                    if (r2 == c + 1) v2.y += o.gamma;
                }
                *(float2*)&Cb[(size_t)r1 * o.ldc + c] = v1;
                *(float2*)&Cb[(size_t)r2 * o.ldc + c] = v2;
                if (o.flags & 16) {
                    zs[mf * 2 + 0] += v1.x + v1.y;
                    zq[mf * 2 + 0] += v1.x * v1.x + v1.y * v1.y;
                    zs[mf * 2 + 1] += v2.x + v2.y;
                    zq[mf * 2 + 1] += v2.x * v2.x + v2.y * v2.y;
                }
            }
        }
    }

    if (o.flags & 16) {
        __syncthreads();
        float* sred = (float*)smem;
        if (t < 128) { sred[t] = 0.f; sred[128 + t] = 0.f; }
        __syncthreads();
#pragma unroll
        for (int q = 0; q < 4; ++q) {
            const int lr = wm * 32 + (lane >> 2) + (q >> 1) * 16 + (q & 1) * 8;
            atomicAdd(&sred[lr], zs[q]);
            atomicAdd(&sred[128 + lr], zq[q]);
        }
        __syncthreads();
        if (t < 128) {
            atomicAdd(&g_bnsum[m0 + t], sred[t]);
            atomicAdd(&g_bnsq[m0 + t], sred[128 + t]);
        }
        __syncthreads();
    }
}

// ---------------- conv launcher kernel --------------------------------------
__global__ void __launch_bounds__(256, 2) tc_conv(OpDesc o) {
    extern __shared__ char smem[];
    gemm_tile(o, blockIdx.z, blockIdx.y * 128, blockIdx.x * 64, smem);
}

// ---------------- chain round bodies ----------------------------------------
__device__ void pow_body(int b, char* smem) {
    const float* Cb = g_cov + (size_t)b * D * D;
    float* v = (float*)smem;
    float* red = v + D;
    const int t = threadIdx.x;
    v[t] = 1.f;
    __syncthreads();
    float lam = 1.f;
    for (int it = 0; it < NPOW; ++it) {
        float w = 0.f;
#pragma unroll 8
        for (int j = 0; j < D; ++j) w = fmaf(Cb[(size_t)j * D + t], v[j], w);
        red[t] = w * w;
        __syncthreads();
        for (int o = 128; o > 0; o >>= 1) {
            if (t < o) red[t] += red[t + o];
            __syncthreads();
        }
        lam = sqrtf(red[0]);
        v[t] = w / fmaxf(lam, 1e-20f);
        __syncthreads();
    }
    if (t == 0) {
        float l = fmaxf(lam, 1e-12f) * 1.05f;   // inflate vs power-iter underestimate
        g_tau[b] = l;
        g_stau[b] = sqrtf(l);
    }
}

__device__ void init_body(int cta, int nct) {
    const int stride = nct * 256;
    const int total = BATCH * D * D / 4;
    for (int i = cta * 256 + (int)threadIdx.x; i < total; i += stride) {
        const int b = i >> 14;            // 16384 float4 per batch
        const int e4 = i & 16383;
        const int row = e4 >> 6;
        const int colb = (e4 & 63) << 2;
        const float invt = 1.f / g_tau[b];
        float4 c = *(const float4*)&g_cov[(size_t)i * 4];
        float4 y0 = make_float4(c.x * invt, c.y * invt, c.z * invt, c.w * invt);
        float4 x = make_float4(c.x * (-1.f / 64.f), c.y * (-1.f / 64.f),
                               c.z * (-1.f / 64.f), c.w * (-1.f / 64.f));
        float4 e = make_float4(0.2f * x.x, 0.2f * x.y, 0.2f * x.z, 0.2f * x.w);
        const float zc = -0.5f * C1 * S1;
        float4 z1 = make_float4(zc * y0.x, zc * y0.y, zc * y0.z, zc * y0.w);
        const int dc = row - colb;
        if (dc >= 0 && dc < 4) {
            ((float*)&e)[dc] += 1.f;
            ((float*)&z1)[dc] += 1.5f * S1;
        }
        *(float4*)&g_Y[(size_t)i * 4] = y0;
        *(float4*)&g_Z[(size_t)i * 4] = x;
        *(float4*)&g_E[(size_t)i * 4] = e;
        *(float4*)&g_Zm[(size_t)i * 4] = z1;
    }
}

__device__ void frob_body(int b, char* smem) {
    float* sm = (float*)smem;
    const float* Ab = g_T + (size_t)b * D * D;
    float ss = 0.f;
    for (int i = threadIdx.x; i < D * D; i += 256) {
        float v = Ab[i];
        ss += v * v;
    }
    sm[threadIdx.x] = ss;
    __syncthreads();
    for (int o = 128; o > 0; o >>= 1) {
        if (threadIdx.x < o) sm[threadIdx.x] += sm[threadIdx.x + o];
        __syncthreads();
    }
    if (threadIdx.x == 0) g_nrm[b] = fmaxf(sqrtf(sm[0]), 1e-12f);
}

// ---------------- chain op schedule -----------------------------------------
__device__ __forceinline__ OpDesc mkq(const float* A, const float* B, float* C,
                                      float alpha, float beta, float gamma,
                                      const float* aDev) {
    OpDesc o;
    o.A = A; o.B = B; o.C = C; o.aux = nullptr; o.alphaDev = aDev;
    o.sA = o.sB = o.sC = 65536LL;
    o.alpha = alpha; o.beta = beta; o.gamma = gamma;
    o.K = D; o.lda = D; o.ldb = D; o.ldc = D; o.Ndim = D; o.flags = 0;
    return o;
}

__device__ int chain_ops(int r, OpDesc* ops) {
    switch (r) {
    case 3:  ops[0] = mkq(g_Y,  g_Y,  g_Y2, -0.5f * C1 * S1, 1.5f * S1, 0.f, nullptr);
             ops[1] = mkq(g_Z,  g_E,  g_E2, 0.25f, 0.f, 1.f, nullptr);          return 2;
    case 4:  ops[0] = mkq(g_Zm, g_Y2, g_T,  -0.5f * C2, 0.f, 1.5f, nullptr);
             ops[1] = mkq(g_Z,  g_E2, g_E,  1.f / 3.f, 0.f, 1.f, nullptr);      return 2;
    case 5:  ops[0] = mkq(g_Y2, g_T,  g_Y,  S2, 0.f, 0.f, nullptr);
             ops[1] = mkq(g_T,  g_Zm, g_Z2, S2, 0.f, 0.f, nullptr);
             ops[2] = mkq(g_Z,  g_E,  g_E2, 0.5f, 0.f, 1.f, nullptr);           return 3;
    case 6:  ops[0] = mkq(g_Z2, g_Y,  g_T,  -0.5f * C3, 0.f, 1.5f, nullptr);
             ops[1] = mkq(g_Z,  g_E2, g_E,  1.f, 0.f, 1.f, nullptr);            return 2;
    case 7:  ops[0] = mkq(g_Y,  g_T,  g_Y2, S3, 0.f, 0.f, nullptr);
             ops[1] = mkq(g_T,  g_Z2, g_Zm, S3, 0.f, 0.f, nullptr);
             ops[2] = mkq(g_E,  g_E,  g_E2, 1.f, 0.f, 0.f, nullptr);            return 3;
    case 8:  ops[0] = mkq(g_Zm, g_Y2, g_T,  -0.5f * C4, 0.f, 1.5f, nullptr);
             ops[1] = mkq(g_E2, g_E2, g_E,  1.f, 0.f, 0.f, nullptr);            return 2;
    case 9:  ops[0] = mkq(g_Y2, g_T,  g_Y,  S4, 0.f, 0.f, nullptr);
             ops[1] = mkq(g_T,  g_Zm, g_Z2, S4, 0.f, 0.f, nullptr);
             ops[2] = mkq(g_E,  g_E,  g_E2, 1.f, 0.f, 0.f, nullptr);            return 3;
    case 10: ops[0] = mkq(g_Z2, g_Y,  g_T,  -0.5f * C5, 0.f, 1.5f, nullptr);
             ops[1] = mkq(g_E2, g_E2, g_E,  1.f, 0.f, 0.f, nullptr);            return 2;
    case 11: ops[0] = mkq(g_Y,  g_T,  g_Y2, S5, 0.f, 0.f, nullptr);
             ops[1] = mkq(g_T,  g_Z2, g_Zm, S5, 0.f, 0.f, nullptr);
             ops[2] = mkq(g_E,  g_E,  g_E2, 1.f, 0.f, 0.f, nullptr);            return 3;
    case 12: ops[0] = mkq(g_Zm, g_Y2, g_T,  -0.5f * C6, 0.f, 1.5f, nullptr);
             ops[1] = mkq(g_E2, g_E2, g_E,  1.f, 0.f, 0.f, nullptr);            return 2;
    case 13: ops[0] = mkq(g_Y2, g_T,  g_Y,  S6, 0.f, 0.f, g_stau);              return 1;
    default: ops[0] = mkq(g_Y,  g_E,  g_T,  1.f, 0.f, 0.f, nullptr);            return 1; // r14: P
    }
}

// ---------------- grid barrier (persistent kernel, all CTAs resident) -------
__device__ __forceinline__ void grid_barrier(int r, int nct) {
    __syncthreads();
    if (threadIdx.x == 0) {
        __threadfence();
        atomicAdd(&g_bar, 1u);
        const unsigned target = (unsigned)(r + 1) * (unsigned)nct;
        while (*(volatile unsigned*)&g_bar < target) __nanosleep(64);
        __threadfence();
    }
    __syncthreads();
}

// ---------------- persistent chain kernel -----------------------------------
__global__ void __launch_bounds__(256, 2) chain_kernel() {
    extern __shared__ char smem[];
    const int nct = gridDim.x;
    const int cta = blockIdx.x;

    for (int r = 0; r < 16; ++r) {
        if (r == 0) {                   // covariance (fp16, K=784)
            OpDesc o;
            o.A = (const float*)g_Zh; o.B = (const float*)g_Zh; o.C = g_cov;
            o.aux = g_rmean; o.alphaDev = nullptr;
            o.sA = (long long)D * M; o.sB = (long long)D * M; o.sC = 65536LL;
            o.alpha = 1.f; o.beta = 0.f; o.gamma = 0.f;
            o.K = M; o.lda = M; o.ldb = M; o.ldc = D; o.Ndim = D; o.flags = 8 | 4;
            for (int it = cta; it < 256; it += nct) {
                const int b = it >> 3, tl = it & 7;
                gemm_tile(o, b, (tl >> 2) * 128, (tl & 3) * 64, smem);
            }
        } else if (r == 1) {
            if (cta < BATCH) pow_body(cta, smem);
        } else if (r == 2) {
            init_body(cta, nct);
        } else if (r == 15) {
            if (cta < BATCH) frob_body(cta, smem);
        } else {
            OpDesc ops[3];
            const int n = chain_ops(r, ops);
            const int total = n * 256;
            for (int it = cta; it < total; it += nct) {
                const int op = it >> 8, rem = it & 255;
                const int b = rem >> 3, tl = rem & 7;
                gemm_tile(ops[op], b, (tl >> 2) * 128, (tl & 3) * 64, smem);
            }
        }
        grid_barrier(r, nct);
    }
}

// ---------------- small kernels ---------------------------------------------
__global__ void zero_stats() {
    g_bnsum[threadIdx.x] = 0.f;
    g_bnsq[threadIdx.x] = 0.f;
    if (threadIdx.x == 0) g_bar = 0u;
}

__global__ void bn_apply(const float* __restrict__ Z,
                         const float* __restrict__ gamma, const float* __restrict__ beta,
                         __half* __restrict__ Zh, float* __restrict__ rmean) {
    const int bd = blockIdx.x;
    const int d = bd & (D - 1);
    const float Ninv = 1.f / (float)(BATCH * M);
    const float mu = g_bnsum[d] * Ninv;
    const float var = g_bnsq[d] * Ninv - mu * mu;
    const float sc = rsqrtf(var + 1e-5f) * gamma[d];
    const float sh = beta[d] - mu * sc;
    const float* row = Z + (size_t)bd * M;
    __half* oh = Zh + (size_t)bd * M;
    float s = 0.f;
    for (int i = threadIdx.x; i < M; i += blockDim.x) {
        float v = fmaxf(row[i] * sc + sh, 0.f);
        oh[i] = __float2half(v);
        s += v;
    }
    __shared__ float sm[128];
    sm[threadIdx.x] = s;
    __syncthreads();
    for (int o = 64; o > 0; o >>= 1) {
        if (threadIdx.x < o) sm[threadIdx.x] += sm[threadIdx.x + o];
        __syncthreads();
    }
    if (threadIdx.x == 0) rmean[bd] = sm[0] * (1.f / (float)M);
}

__global__ void out_triu(const float* __restrict__ Sq, const float* __restrict__ nrm,
                         float* __restrict__ out) {
    const int b = blockIdx.y, i = blockIdx.x;
    const float sc = 1.f + nrm[b];
    const size_t rowoff = (size_t)i * D - (size_t)i * (i - 1) / 2;
    const float* row = Sq + ((size_t)b * D + i) * D;
    float* ob = out + (size_t)b * (D * (D + 1) / 2) + rowoff - i;
    for (int j = i + (int)threadIdx.x; j < D; j += blockDim.x) ob[j] = sc * row[j];
}

// ---------------------------------------------------------------------------
static float* sym_addr(const void* symbol) {
    void* p = nullptr;
    cudaGetSymbolAddress(&p, symbol);
    return (float*)p;
}

extern "C" void kernel_launch(void* const* d_in, const int* in_sizes, int n_in,
                              void* d_out, int out_size) {
    const float* x  = (const float*)d_in[0];
    const float* w  = (const float*)d_in[1];
    const float* gm = (const float*)d_in[2];
    const float* bt = (const float*)d_in[3];
    float* out = (float*)d_out;

    float* Z   = sym_addr(g_Z);
    float* Zh  = sym_addr(g_Zh);
    float* Sq  = sym_addr(g_Y);
    float* rmn = sym_addr(g_rmean);
    float* nrm = sym_addr(g_nrm);

    cudaFuncSetAttribute(tc_conv, cudaFuncAttributeMaxDynamicSharedMemorySize, SMEM_BYTES);
    cudaFuncSetAttribute(chain_kernel, cudaFuncAttributeMaxDynamicSharedMemorySize, SMEM_BYTES);

    // 0. zero BN stats + barrier counter
    zero_stats<<<1, D>>>();
    // 1. conv 1x1 (fp16 single-MMA, trans-B, BN-stat accumulation)
    {
        OpDesc c;
        c.A = w; c.B = x; c.C = Z; c.aux = nullptr; c.alphaDev = nullptr;
        c.sA = 0LL; c.sB = (long long)CIN * M; c.sC = (long long)D * M;
        c.alpha = 1.f; c.beta = 0.f; c.gamma = 0.f;
        c.K = CIN; c.lda = CIN; c.ldb = M; c.ldc = M; c.Ndim = M; c.flags = 1 | 8 | 16;
        tc_conv<<<dim3(13, 2, 32), 256, SMEM_BYTES>>>(c);
    }
    // 2. BN apply + ReLU -> fp16 Zh + row means
    bn_apply<<<BATCH * D, 128>>>(Z, gm, bt, (__half*)Zh, rmn);
    // 3. persistent chain: cov -> power -> init -> scaled NS(6) + expm riders -> P -> frob
    chain_kernel<<<296, 256, SMEM_BYTES>>>();
    // 4. output: y = (1 + ||P||_F) * Sq, upper triangle
    out_triu<<<dim3(D, BATCH), 256>>>(Sq, nrm, out);

    (void)in_sizes; (void)n_in; (void)out_size;
}

// round 11
// speedup vs baseline: 1.1879x; 1.0016x over previous
#include <cuda_runtime.h>
#include <cuda_bf16.h>
#include <cuda_fp16.h>
#include <math.h>
#include <cstdint>

#define BATCH 32
#define D 256
#define CIN 2048
#define M 784
#define NPOW 16

// scaled Newton-Schulz schedule (equioscillation, designed for lmin/lmax >= 0.004)
#define C1 2.79f
#define C2 2.52f
#define C3 1.98f
#define C4 1.35f
#define C5 1.045f
#define C6 1.0005f
#define S1 1.670329f
#define S2 1.587451f
#define S3 1.407125f
#define S4 1.161895f
#define S5 1.022252f
#define S6 1.000250f

typedef unsigned int u32;

// ---------------- scratch (device globals) ---------------------------------
__device__ float g_Z[BATCH * D * M];        // conv acts fp32; later X = -cov/64
__device__ __half g_Zh[BATCH * D * M];      // BN+ReLU activations fp16
__device__ float g_cov[BATCH * D * D];
__device__ float g_Y[BATCH * D * D];        // Y0; final Sq
__device__ float g_Y2[BATCH * D * D];
__device__ float g_Zm[BATCH * D * D];
__device__ float g_Z2[BATCH * D * D];
__device__ float g_T[BATCH * D * D];        // T; final P
__device__ float g_E[BATCH * D * D];
__device__ float g_E2[BATCH * D * D];
__device__ float g_bnsum[D];
__device__ float g_bnsq[D];
__device__ float g_rmean[BATCH * D];
__device__ float g_tau[BATCH];
__device__ float g_stau[BATCH];
__device__ float g_nrm[BATCH];
__device__ unsigned g_bar;

// ---------------- helpers ---------------------------------------------------
__device__ __forceinline__ u32 smem_u32(const void* p) {
    u32 a;
    asm("{ .reg .u64 t; cvta.to.shared.u64 t, %1; cvt.u32.u64 %0, t; }" : "=r"(a) : "l"(p));
    return a;
}
__device__ __forceinline__ u32 pack2(float a, float b) {
    __nv_bfloat162 h = __floats2bfloat162_rn(a, b);
    return *reinterpret_cast<u32*>(&h);
}
__device__ __forceinline__ u32 pack2h(float a, float b) {
    __half2 h = __floats2half2_rn(a, b);
    return *reinterpret_cast<u32*>(&h);
}
__device__ __forceinline__ float lo_res(float a) {
    return a - __bfloat162float(__float2bfloat16_rn(a));
}
__device__ __forceinline__ void ldsm4(u32* r, u32 addr) {
    asm volatile("ldmatrix.sync.aligned.m8n8.x4.shared.b16 {%0,%1,%2,%3}, [%4];"
                 : "=r"(r[0]), "=r"(r[1]), "=r"(r[2]), "=r"(r[3]) : "r"(addr));
}
__device__ __forceinline__ void mma_bf16(float* d, const u32* a, const u32* b) {
    asm volatile(
        "mma.sync.aligned.m16n8k16.row.col.f32.bf16.bf16.f32 "
        "{%0,%1,%2,%3}, {%4,%5,%6,%7}, {%8,%9}, {%0,%1,%2,%3};"
        : "+f"(d[0]), "+f"(d[1]), "+f"(d[2]), "+f"(d[3])
        : "r"(a[0]), "r"(a[1]), "r"(a[2]), "r"(a[3]), "r"(b[0]), "r"(b[1]));
}
__device__ __forceinline__ void mma_fp16(float* d, const u32* a, const u32* b) {
    asm volatile(
        "mma.sync.aligned.m16n8k16.row.col.f32.f16.f16.f32 "
        "{%0,%1,%2,%3}, {%4,%5,%6,%7}, {%8,%9}, {%0,%1,%2,%3};"
        : "+f"(d[0]), "+f"(d[1]), "+f"(d[2]), "+f"(d[3])
        : "r"(a[0]), "r"(a[1]), "r"(a[2]), "r"(a[3]), "r"(b[0]), "r"(b[1]));
}

// ===========================================================================
// GEMM tile body. CTA tile 128x64, 8 warps (4x2), warp tile 32x32,
// K chunks of 64, register-prefetch pipeline.
// Precision: default bf16 hi/lo split (3 mma); flag 8 = single fp16 mma.
// flags: 1=trans B ([K,N] global), 4=COV epi, 8=fp16, 16=BN-stat accum
// General epilogue: C = alpha*(alphaDev?)*acc + beta*A + gamma*diag
// ===========================================================================
struct OpDesc {
    const float* A; const float* B; float* C; const float* aux; const float* alphaDev;
    long long sA, sB, sC;
    float alpha, beta, gamma;
    int K, lda, ldb, ldc, Ndim, flags;
};

#define A_TILE (128 * 144)
#define B_TILE (64 * 144)
#define OFF_AH 0
#define OFF_AL A_TILE
#define OFF_BH (2 * A_TILE)
#define OFF_BL (2 * A_TILE + B_TILE)
#define SMEM_BYTES (2 * A_TILE + 2 * B_TILE)

__device__ void gemm_tile(const OpDesc& o, const int b, const int m0, const int n0,
                          char* smem) {
    const int t    = threadIdx.x;
    const int wid  = t >> 5;
    const int lane = t & 31;
    const u32 sb = smem_u32(smem);
    const bool trans = (o.flags & 1);
    const bool fp16m = (o.flags & 8);

    const float* Ab = nullptr; const __half* AbH = nullptr;
    const float* Bb = nullptr; const __half* BbH = nullptr;
    if (fp16m && !trans) {
        AbH = (const __half*)o.A + (long long)b * o.sA;
        BbH = (const __half*)o.B + (long long)b * o.sB;
    } else {
        Ab = o.A + (long long)b * o.sA;
        Bb = o.B + (long long)b * o.sB;
    }

    float acc[2][4][4];
#pragma unroll
    for (int i = 0; i < 2; ++i)
#pragma unroll
        for (int j = 0; j < 4; ++j)
#pragma unroll
            for (int k = 0; k < 4; ++k) acc[i][j][k] = 0.f;

    const int wm = wid >> 1;
    const int wn = wid & 1;
    const int lAr = (lane & 7) + ((lane >> 3) & 1) * 8;
    const u32 lAc = ((lane >> 4) & 1) * 16;
    const int lBr = (lane & 7) + ((lane >> 4) & 1) * 8;
    const u32 lBc = ((lane >> 3) & 1) * 16;
    const int rgA  = t >> 4;
    const int kq4  = (t & 15) << 2;
    const int cN   = t & 63;
    const int cK0  = (t >> 6) << 4;
    const bool cOK = (n0 + cN) < o.Ndim;

    float4 pfA[8];
    float4 pfB4[4];
    float* pfBs = (float*)pfB4;
    const int nc = (o.K + 63) >> 6;

    auto prefetch = [&](int c) {
        const int kb = c << 6;
        const int kc = min(64, o.K - kb);
        if (kq4 < kc) {
            if (fp16m && !trans) {
#pragma unroll
                for (int i = 0; i < 8; ++i) {
                    uint2 v = *(const uint2*)(AbH + (size_t)(m0 + rgA + i * 16) * o.lda + kb + kq4);
                    pfA[i].x = __uint_as_float(v.x); pfA[i].y = __uint_as_float(v.y);
                }
#pragma unroll
                for (int i = 0; i < 4; ++i) {
                    uint2 v = *(const uint2*)(BbH + (size_t)(n0 + rgA + i * 16) * o.ldb + kb + kq4);
                    pfB4[i].x = __uint_as_float(v.x); pfB4[i].y = __uint_as_float(v.y);
                }
            } else {
#pragma unroll
                for (int i = 0; i < 8; ++i)
                    pfA[i] = *(const float4*)(Ab + (size_t)(m0 + rgA + i * 16) * o.lda + kb + kq4);
                if (!trans) {
#pragma unroll
                    for (int i = 0; i < 4; ++i)
                        pfB4[i] = *(const float4*)(Bb + (size_t)(n0 + rgA + i * 16) * o.ldb + kb + kq4);
                }
            }
        }
        if (trans) {
            const float* Bp = Bb + (size_t)(kb + cK0) * o.ldb + n0 + cN;
#pragma unroll
            for (int j = 0; j < 16; ++j)
                pfBs[j] = cOK ? Bp[(size_t)j * o.ldb] : 0.f;
        }
    };

    prefetch(0);

    for (int c = 0; c < nc; ++c) {
        const int kb = c << 6;
        const int kc = min(64, o.K - kb);
        __syncthreads();
        if (kq4 < kc) {
#pragma unroll
            for (int i = 0; i < 8; ++i) {
                const u32 off = (u32)((rgA + i * 16) * 144 + kq4 * 2);
                float4 v = pfA[i];
                if (!fp16m) {
                    *(uint2*)(smem + OFF_AH + off) = make_uint2(pack2(v.x, v.y), pack2(v.z, v.w));
                    *(uint2*)(smem + OFF_AL + off) =
                        make_uint2(pack2(lo_res(v.x), lo_res(v.y)), pack2(lo_res(v.z), lo_res(v.w)));
                } else if (trans) {
                    *(uint2*)(smem + OFF_AH + off) = make_uint2(pack2h(v.x, v.y), pack2h(v.z, v.w));
                } else {
                    *(uint2*)(smem + OFF_AH + off) =
                        make_uint2(__float_as_uint(v.x), __float_as_uint(v.y));
                }
            }
            if (!trans) {
#pragma unroll
                for (int i = 0; i < 4; ++i) {
                    const u32 off = (u32)((rgA + i * 16) * 144 + kq4 * 2);
                    float4 v = pfB4[i];
                    if (!fp16m) {
                        *(uint2*)(smem + OFF_BH + off) = make_uint2(pack2(v.x, v.y), pack2(v.z, v.w));
                        *(uint2*)(smem + OFF_BL + off) =
                            make_uint2(pack2(lo_res(v.x), lo_res(v.y)), pack2(lo_res(v.z), lo_res(v.w)));
                    } else {
                        *(uint2*)(smem + OFF_BH + off) =
                            make_uint2(__float_as_uint(v.x), __float_as_uint(v.y));
                    }
                }
            }
        }
        if (trans) {
#pragma unroll
            for (int j = 0; j < 4; ++j) {
                const u32 off = (u32)(cN * 144 + (cK0 + j * 4) * 2);
                float v0 = pfBs[j * 4], v1 = pfBs[j * 4 + 1];
                float v2 = pfBs[j * 4 + 2], v3 = pfBs[j * 4 + 3];
                if (!fp16m) {
                    *(uint2*)(smem + OFF_BH + off) = make_uint2(pack2(v0, v1), pack2(v2, v3));
                    *(uint2*)(smem + OFF_BL + off) =
                        make_uint2(pack2(lo_res(v0), lo_res(v1)), pack2(lo_res(v2), lo_res(v3)));
                } else {
                    *(uint2*)(smem + OFF_BH + off) = make_uint2(pack2h(v0, v1), pack2h(v2, v3));
                }
            }
        }
        __syncthreads();
        if (c + 1 < nc) prefetch(c + 1);

        const int ns = kc >> 4;
        if (fp16m) {
            for (int ks = 0; ks < ns; ++ks) {
                const u32 kbyte = (u32)(ks * 32);
                u32 bh[2][4];
#pragma unroll
                for (int pr = 0; pr < 2; ++pr)
                    ldsm4(bh[pr], sb + (u32)((wn * 32 + pr * 16 + lBr) * 144) + kbyte + lBc + OFF_BH);
#pragma unroll
                for (int mf = 0; mf < 2; ++mf) {
                    u32 ah[4];
                    ldsm4(ah, sb + (u32)((wm * 32 + mf * 16 + lAr) * 144) + kbyte + lAc + OFF_AH);
#pragma unroll
                    for (int nf = 0; nf < 4; ++nf)
                        mma_fp16(acc[mf][nf], ah, &bh[nf >> 1][(nf & 1) * 2]);
                }
            }
        } else {
            for (int ks = 0; ks < ns; ++ks) {
                const u32 kbyte = (u32)(ks * 32);
                u32 bh[2][4], bl[2][4];
#pragma unroll
                for (int pr = 0; pr < 2; ++pr) {
                    const u32 ba = sb + (u32)((wn * 32 + pr * 16 + lBr) * 144) + kbyte + lBc;
                    ldsm4(bh[pr], ba + OFF_BH);
                    ldsm4(bl[pr], ba + OFF_BL);
                }
#pragma unroll
                for (int mf = 0; mf < 2; ++mf) {
                    u32 ah[4], al[4];
                    const u32 aa = sb + (u32)((wm * 32 + mf * 16 + lAr) * 144) + kbyte + lAc;
                    ldsm4(ah, aa + OFF_AH);
                    ldsm4(al, aa + OFF_AL);
#pragma unroll
                    for (int nf = 0; nf < 4; ++nf) {
                        const u32* bhf = &bh[nf >> 1][(nf & 1) * 2];
                        const u32* blf = &bl[nf >> 1][(nf & 1) * 2];
                        mma_bf16(acc[mf][nf], ah, bhf);
                        mma_bf16(acc[mf][nf], ah, blf);
                        mma_bf16(acc[mf][nf], al, bhf);
                    }
                }
            }
        }
    }

    // ---------------- epilogue ----------------
    const float aeff = o.alpha * (o.alphaDev ? o.alphaDev[b] : 1.f);
    float* Cb = o.C + (long long)b * o.sC;
    const int mb = m0 + wm * 32 + (lane >> 2);
    const int cb = n0 + wn * 32 + (lane & 3) * 2;

    float zs[4] = {0.f, 0.f, 0.f, 0.f}, zq[4] = {0.f, 0.f, 0.f, 0.f};

#pragma unroll
    for (int mf = 0; mf < 2; ++mf) {
#pragma unroll
        for (int nf = 0; nf < 4; ++nf) {
            const int c  = cb + nf * 8;
            const int r1 = mb + mf * 16;
            const int r2 = r1 + 8;
            float d0 = acc[mf][nf][0], d1 = acc[mf][nf][1];
            float d2 = acc[mf][nf][2], d3 = acc[mf][nf][3];

            if (o.flags & 4) {
                const float* rm = o.aux + b * D;
                const float invM = 1.f / (float)M;
                const float rc0 = rm[c], rc1 = rm[c + 1];
                *(float2*)&Cb[(size_t)r1 * o.ldc + c] =
                    make_float2(d0 * invM - rm[r1] * rc0, d1 * invM - rm[r1] * rc1);
                *(float2*)&Cb[(size_t)r2 * o.ldc + c] =
                    make_float2(d2 * invM - rm[r2] * rc0, d3 * invM - rm[r2] * rc1);
            } else {
                if (c >= o.Ndim) continue;
                float2 v1 = make_float2(aeff * d0, aeff * d1);
                float2 v2 = make_float2(aeff * d2, aeff * d3);
                if (o.beta != 0.f) {
                    float2 a1 = *(const float2*)&Ab[(size_t)r1 * o.lda + c];
                    float2 a2 = *(const float2*)&Ab[(size_t)r2 * o.lda + c];
                    v1.x += o.beta * a1.x; v1.y += o.beta * a1.y;
                    v2.x += o.beta * a2.x; v2.y += o.beta * a2.y;
                }
                if (o.gamma != 0.f) {
                    if (r1 == c)     v1.x += o.gamma;
                    if (r1 == c + 1) v1.y += o.gamma;
                    if (r2 == c)     v2.x += o.gamma;
                    if (r2 == c + 1) v2.y += o.gamma;
                }
                *(float2*)&Cb[(size_t)r1 * o.ldc + c] = v1;
                *(float2*)&Cb[(size_t)r2 * o.ldc + c] = v2;
                if (o.flags & 16) {
                    zs[mf * 2 + 0] += v1.x + v1.y;
                    zq[mf * 2 + 0] += v1.x * v1.x + v1.y * v1.y;
                    zs[mf * 2 + 1] += v2.x + v2.y;
                    zq[mf * 2 + 1] += v2.x * v2.x + v2.y * v2.y;
                }
            }
        }
    }

    if (o.flags & 16) {
        __syncthreads();
        float* sred = (float*)smem;
        if (t < 128) { sred[t] = 0.f; sred[128 + t] = 0.f; }
        __syncthreads();
#pragma unroll
        for (int q = 0; q < 4; ++q) {
            const int lr = wm * 32 + (lane >> 2) + (q >> 1) * 16 + (q & 1) * 8;
            atomicAdd(&sred[lr], zs[q]);
            atomicAdd(&sred[128 + lr], zq[q]);
        }
        __syncthreads();
        if (t < 128) {
            atomicAdd(&g_bnsum[m0 + t], sred[t]);
            atomicAdd(&g_bnsq[m0 + t], sred[128 + t]);
        }
        __syncthreads();
    }
}

// ---------------- conv launcher kernel --------------------------------------
__global__ void __launch_bounds__(256, 2) tc_conv(OpDesc o) {
    extern __shared__ char smem[];
    gemm_tile(o, blockIdx.z, blockIdx.y * 128, blockIdx.x * 64, smem);
}

// ---------------- chain round bodies ----------------------------------------
__device__ void pow_body(int b, char* smem) {
    const float* Cb = g_cov + (size_t)b * D * D;
    float* v = (float*)smem;
    float* red = v + D;
    const int t = threadIdx.x;
    v[t] = 1.f;
    __syncthreads();
    float lam = 1.f;
    for (int it = 0; it < NPOW; ++it) {
        float w = 0.f;
#pragma unroll 8
        for (int j = 0; j < D; ++j) w = fmaf(Cb[(size_t)j * D + t], v[j], w);
        red[t] = w * w;
        __syncthreads();
        for (int o = 128; o > 0; o >>= 1) {
            if (t < o) red[t] += red[t + o];
            __syncthreads();
        }
        lam = sqrtf(red[0]);
        v[t] = w / fmaxf(lam, 1e-20f);
        __syncthreads();
    }
    if (t == 0) {
        float l = fmaxf(lam, 1e-12f) * 1.05f;   // inflate vs power-iter underestimate
        g_tau[b] = l;
        g_stau[b] = sqrtf(l);
    }
}

__device__ void init_body(int cta, int nct) {
    const int stride = nct * 256;
    const int total = BATCH * D * D / 4;
    for (int i = cta * 256 + (int)threadIdx.x; i < total; i += stride) {
        const int b = i >> 14;            // 16384 float4 per batch
        const int e4 = i & 16383;
        const int row = e4 >> 6;
        const int colb = (e4 & 63) << 2;
        const float invt = 1.f / g_tau[b];
        float4 c = *(const float4*)&g_cov[(size_t)i * 4];
        float4 y0 = make_float4(c.x * invt, c.y * invt, c.z * invt, c.w * invt);
        float4 x = make_float4(c.x * (-1.f / 64.f), c.y * (-1.f / 64.f),
                               c.z * (-1.f / 64.f), c.w * (-1.f / 64.f));
        float4 e = make_float4(0.2f * x.x, 0.2f * x.y, 0.2f * x.z, 0.2f * x.w);
        const float zc = -0.5f * C1 * S1;
        float4 z1 = make_float4(zc * y0.x, zc * y0.y, zc * y0.z, zc * y0.w);
        const int dc = row - colb;
        if (dc >= 0 && dc < 4) {
            ((float*)&e)[dc] += 1.f;
            ((float*)&z1)[dc] += 1.5f * S1;
        }
        *(float4*)&g_Y[(size_t)i * 4] = y0;
        *(float4*)&g_Z[(size_t)i * 4] = x;
        *(float4*)&g_E[(size_t)i * 4] = e;
        *(float4*)&g_Zm[(size_t)i * 4] = z1;
    }
}

__device__ void frob_body(int b, char* smem) {
    float* sm = (float*)smem;
    const float* Ab = g_T + (size_t)b * D * D;
    float ss = 0.f;
    for (int i = threadIdx.x; i < D * D; i += 256) {
        float v = Ab[i];
        ss += v * v;
    }
    sm[threadIdx.x] = ss;
    __syncthreads();
    for (int o = 128; o > 0; o >>= 1) {
        if (threadIdx.x < o) sm[threadIdx.x] += sm[threadIdx.x + o];
        __syncthreads();
    }
    if (threadIdx.x == 0) g_nrm[b] = fmaxf(sqrtf(sm[0]), 1e-12f);
}

// ---------------- chain op schedule -----------------------------------------
__device__ __forceinline__ OpDesc mkq(const float* A, const float* B, float* C,
                                      float alpha, float beta, float gamma,
                                      const float* aDev) {
    OpDesc o;
    o.A = A; o.B = B; o.C = C; o.aux = nullptr; o.alphaDev = aDev;
    o.sA = o.sB = o.sC = 65536LL;
    o.alpha = alpha; o.beta = beta; o.gamma = gamma;
    o.K = D; o.lda = D; o.ldb = D; o.ldc = D; o.Ndim = D; o.flags = 0;
    return o;
}

__device__ int chain_ops(int r, OpDesc* ops) {
    switch (r) {
    case 3:  ops[0] = mkq(g_Y,  g_Y,  g_Y2, -0.5f * C1 * S1, 1.5f * S1, 0.f, nullptr);
             ops[1] = mkq(g_Z,  g_E,  g_E2, 0.25f, 0.f, 1.f, nullptr);          return 2;
    case 4:  ops[0] = mkq(g_Zm, g_Y2, g_T,  -0.5f * C2, 0.f, 1.5f, nullptr);
             ops[1] = mkq(g_Z,  g_E2, g_E,  1.f / 3.f, 0.f, 1.f, nullptr);      return 2;
    case 5:  ops[0] = mkq(g_Y2, g_T,  g_Y,  S2, 0.f, 0.f, nullptr);
             ops[1] = mkq(g_T,  g_Zm, g_Z2, S2, 0.f, 0.f, nullptr);
             ops[2] = mkq(g_Z,  g_E,  g_E2, 0.5f, 0.f, 1.f, nullptr);           return 3;
    case 6:  ops[0] = mkq(g_Z2, g_Y,  g_T,  -0.5f * C3, 0.f, 1.5f, nullptr);
             ops[1] = mkq(g_Z,  g_E2, g_E,  1.f, 0.f, 1.f, nullptr);            return 2;
    case 7:  ops[0] = mkq(g_Y,  g_T,  g_Y2, S3, 0.f, 0.f, nullptr);
             ops[1] = mkq(g_T,  g_Z2, g_Zm, S3, 0.f, 0.f, nullptr);
             ops[2] = mkq(g_E,  g_E,  g_E2, 1.f, 0.f, 0.f, nullptr);            return 3;
    case 8:  ops[0] = mkq(g_Zm, g_Y2, g_T,  -0.5f * C4, 0.f, 1.5f, nullptr);
             ops[1] = mkq(g_E2, g_E2, g_E,  1.f, 0.f, 0.f, nullptr);            return 2;
    case 9:  ops[0] = mkq(g_Y2, g_T,  g_Y,  S4, 0.f, 0.f, nullptr);
             ops[1] = mkq(g_T,  g_Zm, g_Z2, S4, 0.f, 0.f, nullptr);
             ops[2] = mkq(g_E,  g_E,  g_E2, 1.f, 0.f, 0.f, nullptr);            return 3;
    case 10: ops[0] = mkq(g_Z2, g_Y,  g_T,  -0.5f * C5, 0.f, 1.5f, nullptr);
             ops[1] = mkq(g_E2, g_E2, g_E,  1.f, 0.f, 0.f, nullptr);            return 2;
    case 11: ops[0] = mkq(g_Y,  g_T,  g_Y2, S5, 0.f, 0.f, nullptr);
             ops[1] = mkq(g_T,  g_Z2, g_Zm, S5, 0.f, 0.f, nullptr);
             ops[2] = mkq(g_E,  g_E,  g_E2, 1.f, 0.f, 0.f, nullptr);            return 3;
    case 12: ops[0] = mkq(g_Zm, g_Y2, g_T,  -0.5f * C6, 0.f, 1.5f, nullptr);
             ops[1] = mkq(g_E2, g_E2, g_E,  1.f, 0.f, 0.f, nullptr);            return 2;
    case 13: ops[0] = mkq(g_Y2, g_T,  g_Y,  S6, 0.f, 0.f, g_stau);              return 1;
    default: ops[0] = mkq(g_Y,  g_E,  g_T,  1.f, 0.f, 0.f, nullptr);            return 1; // r14: P
    }
}

// ---------------- grid barrier (persistent kernel, all CTAs resident) -------
__device__ __forceinline__ void grid_barrier(int r, int nct) {
    __syncthreads();
    if (threadIdx.x == 0) {
        __threadfence();
        atomicAdd(&g_bar, 1u);
        const unsigned target = (unsigned)(r + 1) * (unsigned)nct;
        while (*(volatile unsigned*)&g_bar < target) __nanosleep(64);
        __threadfence();
    }
    __syncthreads();
}

// ---------------- persistent chain kernel -----------------------------------
__global__ void __launch_bounds__(256, 2) chain_kernel() {
    extern __shared__ char smem[];
    const int nct = gridDim.x;
    const int cta = blockIdx.x;

    for (int r = 0; r < 16; ++r) {
        if (r == 0) {                   // covariance (fp16, K=784)
            OpDesc o;
            o.A = (const float*)g_Zh; o.B = (const float*)g_Zh; o.C = g_cov;
            o.aux = g_rmean; o.alphaDev = nullptr;
            o.sA = (long long)D * M; o.sB = (long long)D * M; o.sC = 65536LL;
            o.alpha = 1.f; o.beta = 0.f; o.gamma = 0.f;
            o.K = M; o.lda = M; o.ldb = M; o.ldc = D; o.Ndim = D; o.flags = 8 | 4;
            for (int it = cta; it < 256; it += nct) {
                const int b = it >> 3, tl = it & 7;
                gemm_tile(o, b, (tl >> 2) * 128, (tl & 3) * 64, smem);
            }
        } else if (r == 1) {
            if (cta < BATCH) pow_body(cta, smem);
        } else if (r == 2) {
            init_body(cta, nct);
        } else if (r == 15) {
            if (cta < BATCH) frob_body(cta, smem);
        } else {
            OpDesc ops[3];
            const int n = chain_ops(r, ops);
            const int total = n * 256;
            for (int it = cta; it < total; it += nct) {
                const int op = it >> 8, rem = it & 255;
                const int b = rem >> 3, tl = rem & 7;
                gemm_tile(ops[op], b, (tl >> 2) * 128, (tl & 3) * 64, smem);
            }
        }
        grid_barrier(r, nct);
    }
}

// ---------------- small kernels ---------------------------------------------
__global__ void zero_stats() {
    g_bnsum[threadIdx.x] = 0.f;
    g_bnsq[threadIdx.x] = 0.f;
    if (threadIdx.x == 0) g_bar = 0u;
}

__global__ void bn_apply(const float* __restrict__ Z,
                         const float* __restrict__ gamma, const float* __restrict__ beta,
                         __half* __restrict__ Zh, float* __restrict__ rmean) {
    const int bd = blockIdx.x;
    const int d = bd & (D - 1);
    const float Ninv = 1.f / (float)(BATCH * M);
    const float mu = g_bnsum[d] * Ninv;
    const float var = g_bnsq[d] * Ninv - mu * mu;
    const float sc = rsqrtf(var + 1e-5f) * gamma[d];
    const float sh = beta[d] - mu * sc;
    const float* row = Z + (size_t)bd * M;
    __half* oh = Zh + (size_t)bd * M;
    float s = 0.f;
    for (int i = threadIdx.x; i < M; i += blockDim.x) {
        float v = fmaxf(row[i] * sc + sh, 0.f);
        oh[i] = __float2half(v);
        s += v;
    }
    __shared__ float sm[128];
    sm[threadIdx.x] = s;
    __syncthreads();
    for (int o = 64; o > 0; o >>= 1) {
        if (threadIdx.x < o) sm[threadIdx.x] += sm[threadIdx.x + o];
        __syncthreads();
    }
    if (threadIdx.x == 0) rmean[bd] = sm[0] * (1.f / (float)M);
}

__global__ void out_triu(const float* __restrict__ Sq, const float* __restrict__ nrm,
                         float* __restrict__ out) {
    const int b = blockIdx.y, i = blockIdx.x;
    const float sc = 1.f + nrm[b];
    const size_t rowoff = (size_t)i * D - (size_t)i * (i - 1) / 2;
    const float* row = Sq + ((size_t)b * D + i) * D;
    float* ob = out + (size_t)b * (D * (D + 1) / 2) + rowoff - i;
    for (int j = i + (int)threadIdx.x; j < D; j += blockDim.x) ob[j] = sc * row[j];
}

// ---------------------------------------------------------------------------
static float* sym_addr(const void* symbol) {
    void* p = nullptr;
    cudaGetSymbolAddress(&p, symbol);
    return (float*)p;
}

extern "C" void kernel_launch(void* const* d_in, const int* in_sizes, int n_in,
                              void* d_out, int out_size) {
    const float* x  = (const float*)d_in[0];
    const float* w  = (const float*)d_in[1];
    const float* gm = (const float*)d_in[2];
    const float* bt = (const float*)d_in[3];
    float* out = (float*)d_out;

    float* Z   = sym_addr(g_Z);
    float* Zh  = sym_addr(g_Zh);
    float* Sq  = sym_addr(g_Y);
    float* rmn = sym_addr(g_rmean);
    float* nrm = sym_addr(g_nrm);

    cudaFuncSetAttribute(tc_conv, cudaFuncAttributeMaxDynamicSharedMemorySize, SMEM_BYTES);
    cudaFuncSetAttribute(chain_kernel, cudaFuncAttributeMaxDynamicSharedMemorySize, SMEM_BYTES);

    // 0. zero BN stats + barrier counter
    zero_stats<<<1, D>>>();
    // 1. conv 1x1 (fp16 single-MMA, trans-B, BN-stat accumulation)
    {
        OpDesc c;
        c.A = w; c.B = x; c.C = Z; c.aux = nullptr; c.alphaDev = nullptr;
        c.sA = 0LL; c.sB = (long long)CIN * M; c.sC = (long long)D * M;
        c.alpha = 1.f; c.beta = 0.f; c.gamma = 0.f;
        c.K = CIN; c.lda = CIN; c.ldb = M; c.ldc = M; c.Ndim = M; c.flags = 1 | 8 | 16;
        tc_conv<<<dim3(13, 2, 32), 256, SMEM_BYTES>>>(c);
    }
    // 2. BN apply + ReLU -> fp16 Zh + row means
    bn_apply<<<BATCH * D, 128>>>(Z, gm, bt, (__half*)Zh, rmn);
    // 3. persistent chain: cov -> power -> init -> scaled NS(6) + expm riders -> P -> frob
    chain_kernel<<<296, 256, SMEM_BYTES>>>();
    // 4. output: y = (1 + ||P||_F) * Sq, upper triangle
    out_triu<<<dim3(D, BATCH), 256>>>(Sq, nrm, out);

    (void)in_sizes; (void)n_in; (void)out_size;
}

// round 12
// speedup vs baseline: 1.3609x; 1.1456x over previous
#include <cuda_runtime.h>
#include <cuda_bf16.h>
#include <cuda_fp16.h>
#include <math.h>
#include <cstdint>

#define BATCH 32
#define D 256
#define CIN 2048
#define M 784
#define NPOW 16

// scaled Newton-Schulz schedule (equioscillation, designed for lmin/lmax >= 0.004)
#define C1 2.79f
#define C2 2.52f
#define C3 1.98f
#define C4 1.35f
#define C5 1.045f
#define C6 1.0005f
#define S1 1.670329f
#define S2 1.587451f
#define S3 1.407125f
#define S4 1.161895f
#define S5 1.022252f
#define S6 1.000250f

typedef unsigned int u32;

// ---------------- scratch (device globals) ---------------------------------
__device__ float g_Z[BATCH * D * M];        // conv acts fp32; later X = -cov/64
__device__ __half g_Zh[BATCH * D * M];      // BN+ReLU activations fp16
__device__ float g_cov[BATCH * D * D];
__device__ float g_Y[BATCH * D * D];        // Y0; final Sq
__device__ float g_Y2[BATCH * D * D];
__device__ float g_Zm[BATCH * D * D];
__device__ float g_Z2[BATCH * D * D];
__device__ float g_T[BATCH * D * D];        // T; final P
__device__ float g_E[BATCH * D * D];
__device__ float g_E2[BATCH * D * D];
__device__ float g_bnsum[D];
__device__ float g_bnsq[D];
__device__ float g_rmean[BATCH * D];
__device__ float g_stau[BATCH];
__device__ float g_nrm[BATCH];
__device__ unsigned g_barb[BATCH];

// ---------------- helpers ---------------------------------------------------
__device__ __forceinline__ u32 smem_u32(const void* p) {
    u32 a;
    asm("{ .reg .u64 t; cvta.to.shared.u64 t, %1; cvt.u32.u64 %0, t; }" : "=r"(a) : "l"(p));
    return a;
}
__device__ __forceinline__ u32 pack2(float a, float b) {
    __nv_bfloat162 h = __floats2bfloat162_rn(a, b);
    return *reinterpret_cast<u32*>(&h);
}
__device__ __forceinline__ u32 pack2h(float a, float b) {
    __half2 h = __floats2half2_rn(a, b);
    return *reinterpret_cast<u32*>(&h);
}
__device__ __forceinline__ float lo_res(float a) {
    return a - __bfloat162float(__float2bfloat16_rn(a));
}
__device__ __forceinline__ void ldsm4(u32* r, u32 addr) {
    asm volatile("ldmatrix.sync.aligned.m8n8.x4.shared.b16 {%0,%1,%2,%3}, [%4];"
                 : "=r"(r[0]), "=r"(r[1]), "=r"(r[2]), "=r"(r[3]) : "r"(addr));
}
__device__ __forceinline__ void mma_bf16(float* d, const u32* a, const u32* b) {
    asm volatile(
        "mma.sync.aligned.m16n8k16.row.col.f32.bf16.bf16.f32 "
        "{%0,%1,%2,%3}, {%4,%5,%6,%7}, {%8,%9}, {%0,%1,%2,%3};"
        : "+f"(d[0]), "+f"(d[1]), "+f"(d[2]), "+f"(d[3])
        : "r"(a[0]), "r"(a[1]), "r"(a[2]), "r"(a[3]), "r"(b[0]), "r"(b[1]));
}
__device__ __forceinline__ void mma_fp16(float* d, const u32* a, const u32* b) {
    asm volatile(
        "mma.sync.aligned.m16n8k16.row.col.f32.f16.f16.f32 "
        "{%0,%1,%2,%3}, {%4,%5,%6,%7}, {%8,%9}, {%0,%1,%2,%3};"
        : "+f"(d[0]), "+f"(d[1]), "+f"(d[2]), "+f"(d[3])
        : "r"(a[0]), "r"(a[1]), "r"(a[2]), "r"(a[3]), "r"(b[0]), "r"(b[1]));
}

// ===========================================================================
// GEMM tile body. CTA tile 128x64, 8 warps (4x2), warp tile 32x32,
// K chunks of 64, register-prefetch pipeline.
// Precision: default bf16 hi/lo split (3 mma); flag 8 = single fp16 mma.
// flags: 1=trans B ([K,N] global), 4=COV epi, 8=fp16, 16=BN-stat accum
// General epilogue: C = alpha*(alphaDev?)*acc + beta*A + gamma*diag
// ===========================================================================
struct OpDesc {
    const float* A; const float* B; float* C; const float* aux; const float* alphaDev;
    long long sA, sB, sC;
    float alpha, beta, gamma;
    int K, lda, ldb, ldc, Ndim, flags;
};

#define A_TILE (128 * 144)
#define B_TILE (64 * 144)
#define OFF_AH 0
#define OFF_AL A_TILE
#define OFF_BH (2 * A_TILE)
#define OFF_BL (2 * A_TILE + B_TILE)
#define SMEM_BYTES (2 * A_TILE + 2 * B_TILE)

__device__ void gemm_tile(const OpDesc& o, const int b, const int m0, const int n0,
                          char* smem) {
    const int t    = threadIdx.x;
    const int wid  = t >> 5;
    const int lane = t & 31;
    const u32 sb = smem_u32(smem);
    const bool trans = (o.flags & 1);
    const bool fp16m = (o.flags & 8);

    const float* Ab = nullptr; const __half* AbH = nullptr;
    const float* Bb = nullptr; const __half* BbH = nullptr;
    if (fp16m && !trans) {
        AbH = (const __half*)o.A + (long long)b * o.sA;
        BbH = (const __half*)o.B + (long long)b * o.sB;
    } else {
        Ab = o.A + (long long)b * o.sA;
        Bb = o.B + (long long)b * o.sB;
    }

    float acc[2][4][4];
#pragma unroll
    for (int i = 0; i < 2; ++i)
#pragma unroll
        for (int j = 0; j < 4; ++j)
#pragma unroll
            for (int k = 0; k < 4; ++k) acc[i][j][k] = 0.f;

    const int wm = wid >> 1;
    const int wn = wid & 1;
    const int lAr = (lane & 7) + ((lane >> 3) & 1) * 8;
    const u32 lAc = ((lane >> 4) & 1) * 16;
    const int lBr = (lane & 7) + ((lane >> 4) & 1) * 8;
    const u32 lBc = ((lane >> 3) & 1) * 16;
    const int rgA  = t >> 4;
    const int kq4  = (t & 15) << 2;
    const int cN   = t & 63;
    const int cK0  = (t >> 6) << 4;
    const bool cOK = (n0 + cN) < o.Ndim;

    float4 pfA[8];
    float4 pfB4[4];
    float* pfBs = (float*)pfB4;
    const int nc = (o.K + 63) >> 6;

    auto prefetch = [&](int c) {
        const int kb = c << 6;
        const int kc = min(64, o.K - kb);
        if (kq4 < kc) {
            if (fp16m && !trans) {
#pragma unroll
                for (int i = 0; i < 8; ++i) {
                    uint2 v = *(const uint2*)(AbH + (size_t)(m0 + rgA + i * 16) * o.lda + kb + kq4);
                    pfA[i].x = __uint_as_float(v.x); pfA[i].y = __uint_as_float(v.y);
                }
#pragma unroll
                for (int i = 0; i < 4; ++i) {
                    uint2 v = *(const uint2*)(BbH + (size_t)(n0 + rgA + i * 16) * o.ldb + kb + kq4);
                    pfB4[i].x = __uint_as_float(v.x); pfB4[i].y = __uint_as_float(v.y);
                }
            } else {
#pragma unroll
                for (int i = 0; i < 8; ++i)
                    pfA[i] = *(const float4*)(Ab + (size_t)(m0 + rgA + i * 16) * o.lda + kb + kq4);
                if (!trans) {
#pragma unroll
                    for (int i = 0; i < 4; ++i)
                        pfB4[i] = *(const float4*)(Bb + (size_t)(n0 + rgA + i * 16) * o.ldb + kb + kq4);
                }
            }
        }
        if (trans) {
            const float* Bp = Bb + (size_t)(kb + cK0) * o.ldb + n0 + cN;
#pragma unroll
            for (int j = 0; j < 16; ++j)
                pfBs[j] = cOK ? Bp[(size_t)j * o.ldb] : 0.f;
        }
    };

    prefetch(0);

    for (int c = 0; c < nc; ++c) {
        const int kb = c << 6;
        const int kc = min(64, o.K - kb);
        __syncthreads();
        if (kq4 < kc) {
#pragma unroll
            for (int i = 0; i < 8; ++i) {
                const u32 off = (u32)((rgA + i * 16) * 144 + kq4 * 2);
                float4 v = pfA[i];
                if (!fp16m) {
                    *(uint2*)(smem + OFF_AH + off) = make_uint2(pack2(v.x, v.y), pack2(v.z, v.w));
                    *(uint2*)(smem + OFF_AL + off) =
                        make_uint2(pack2(lo_res(v.x), lo_res(v.y)), pack2(lo_res(v.z), lo_res(v.w)));
                } else if (trans) {
                    *(uint2*)(smem + OFF_AH + off) = make_uint2(pack2h(v.x, v.y), pack2h(v.z, v.w));
                } else {
                    *(uint2*)(smem + OFF_AH + off) =
                        make_uint2(__float_as_uint(v.x), __float_as_uint(v.y));
                }
            }
            if (!trans) {
#pragma unroll
                for (int i = 0; i < 4; ++i) {
                    const u32 off = (u32)((rgA + i * 16) * 144 + kq4 * 2);
                    float4 v = pfB4[i];
                    if (!fp16m) {
                        *(uint2*)(smem + OFF_BH + off) = make_uint2(pack2(v.x, v.y), pack2(v.z, v.w));
                        *(uint2*)(smem + OFF_BL + off) =
                            make_uint2(pack2(lo_res(v.x), lo_res(v.y)), pack2(lo_res(v.z), lo_res(v.w)));
                    } else {
                        *(uint2*)(smem + OFF_BH + off) =
                            make_uint2(__float_as_uint(v.x), __float_as_uint(v.y));
                    }
                }
            }
        }
        if (trans) {
#pragma unroll
            for (int j = 0; j < 4; ++j) {
                const u32 off = (u32)(cN * 144 + (cK0 + j * 4) * 2);
                float v0 = pfBs[j * 4], v1 = pfBs[j * 4 + 1];
                float v2 = pfBs[j * 4 + 2], v3 = pfBs[j * 4 + 3];
                if (!fp16m) {
                    *(uint2*)(smem + OFF_BH + off) = make_uint2(pack2(v0, v1), pack2(v2, v3));
                    *(uint2*)(smem + OFF_BL + off) =
                        make_uint2(pack2(lo_res(v0), lo_res(v1)), pack2(lo_res(v2), lo_res(v3)));
                } else {
                    *(uint2*)(smem + OFF_BH + off) = make_uint2(pack2h(v0, v1), pack2h(v2, v3));
                }
            }
        }
        __syncthreads();
        if (c + 1 < nc) prefetch(c + 1);

        const int ns = kc >> 4;
        if (fp16m) {
            for (int ks = 0; ks < ns; ++ks) {
                const u32 kbyte = (u32)(ks * 32);
                u32 bh[2][4];
#pragma unroll
                for (int pr = 0; pr < 2; ++pr)
                    ldsm4(bh[pr], sb + (u32)((wn * 32 + pr * 16 + lBr) * 144) + kbyte + lBc + OFF_BH);
#pragma unroll
                for (int mf = 0; mf < 2; ++mf) {
                    u32 ah[4];
                    ldsm4(ah, sb + (u32)((wm * 32 + mf * 16 + lAr) * 144) + kbyte + lAc + OFF_AH);
#pragma unroll
                    for (int nf = 0; nf < 4; ++nf)
                        mma_fp16(acc[mf][nf], ah, &bh[nf >> 1][(nf & 1) * 2]);
                }
            }
        } else {
            for (int ks = 0; ks < ns; ++ks) {
                const u32 kbyte = (u32)(ks * 32);
                u32 bh[2][4], bl[2][4];
#pragma unroll
                for (int pr = 0; pr < 2; ++pr) {
                    const u32 ba = sb + (u32)((wn * 32 + pr * 16 + lBr) * 144) + kbyte + lBc;
                    ldsm4(bh[pr], ba + OFF_BH);
                    ldsm4(bl[pr], ba + OFF_BL);
                }
#pragma unroll
                for (int mf = 0; mf < 2; ++mf) {
                    u32 ah[4], al[4];
                    const u32 aa = sb + (u32)((wm * 32 + mf * 16 + lAr) * 144) + kbyte + lAc;
                    ldsm4(ah, aa + OFF_AH);
                    ldsm4(al, aa + OFF_AL);
#pragma unroll
                    for (int nf = 0; nf < 4; ++nf) {
                        const u32* bhf = &bh[nf >> 1][(nf & 1) * 2];
                        const u32* blf = &bl[nf >> 1][(nf & 1) * 2];
                        mma_bf16(acc[mf][nf], ah, bhf);
                        mma_bf16(acc[mf][nf], ah, blf);
                        mma_bf16(acc[mf][nf], al, bhf);
                    }
                }
            }
        }
    }

    // ---------------- epilogue ----------------
    const float aeff = o.alpha * (o.alphaDev ? o.alphaDev[b] : 1.f);
    float* Cb = o.C + (long long)b * o.sC;
    const int mb = m0 + wm * 32 + (lane >> 2);
    const int cb = n0 + wn * 32 + (lane & 3) * 2;

    float zs[4] = {0.f, 0.f, 0.f, 0.f}, zq[4] = {0.f, 0.f, 0.f, 0.f};

#pragma unroll
    for (int mf = 0; mf < 2; ++mf) {
#pragma unroll
        for (int nf = 0; nf < 4; ++nf) {
            const int c  = cb + nf * 8;
            const int r1 = mb + mf * 16;
            const int r2 = r1 + 8;
            float d0 = acc[mf][nf][0], d1 = acc[mf][nf][1];
            float d2 = acc[mf][nf][2], d3 = acc[mf][nf][3];

            if (o.flags & 4) {
                const float* rm = o.aux + b * D;
                const float invM = 1.f / (float)M;
                const float rc0 = rm[c], rc1 = rm[c + 1];
                *(float2*)&Cb[(size_t)r1 * o.ldc + c] =
                    make_float2(d0 * invM - rm[r1] * rc0, d1 * invM - rm[r1] * rc1);
                *(float2*)&Cb[(size_t)r2 * o.ldc + c] =
                    make_float2(d2 * invM - rm[r2] * rc0, d3 * invM - rm[r2] * rc1);
            } else {
                if (c >= o.Ndim) continue;
                float2 v1 = make_float2(aeff * d0, aeff * d1);
                float2 v2 = make_float2(aeff * d2, aeff * d3);
                if (o.beta != 0.f) {
                    float2 a1 = *(const float2*)&Ab[(size_t)r1 * o.lda + c];
                    float2 a2 = *(const float2*)&Ab[(size_t)r2 * o.lda + c];
                    v1.x += o.beta * a1.x; v1.y += o.beta * a1.y;
                    v2.x += o.beta * a2.x; v2.y += o.beta * a2.y;
                }
                if (o.gamma != 0.f) {
                    if (r1 == c)     v1.x += o.gamma;
                    if (r1 == c + 1) v1.y += o.gamma;
                    if (r2 == c)     v2.x += o.gamma;
                    if (r2 == c + 1) v2.y += o.gamma;
                }
                *(float2*)&Cb[(size_t)r1 * o.ldc + c] = v1;
                *(float2*)&Cb[(size_t)r2 * o.ldc + c] = v2;
                if (o.flags & 16) {
                    zs[mf * 2 + 0] += v1.x + v1.y;
                    zq[mf * 2 + 0] += v1.x * v1.x + v1.y * v1.y;
                    zs[mf * 2 + 1] += v2.x + v2.y;
                    zq[mf * 2 + 1] += v2.x * v2.x + v2.y * v2.y;
                }
            }
        }
    }

    if (o.flags & 16) {
        __syncthreads();
        float* sred = (float*)smem;
        if (t < 128) { sred[t] = 0.f; sred[128 + t] = 0.f; }
        __syncthreads();
#pragma unroll
        for (int q = 0; q < 4; ++q) {
            const int lr = wm * 32 + (lane >> 2) + (q >> 1) * 16 + (q & 1) * 8;
            atomicAdd(&sred[lr], zs[q]);
            atomicAdd(&sred[128 + lr], zq[q]);
        }
        __syncthreads();
        if (t < 128) {
            atomicAdd(&g_bnsum[m0 + t], sred[t]);
            atomicAdd(&g_bnsq[m0 + t], sred[128 + t]);
        }
        __syncthreads();
    }
}

// ---------------- conv launcher kernel --------------------------------------
__global__ void __launch_bounds__(256, 2) tc_conv(OpDesc o) {
    extern __shared__ char smem[];
    gemm_tile(o, blockIdx.z, blockIdx.y * 128, blockIdx.x * 64, smem);
}

// ---------------- chain round bodies ----------------------------------------
__device__ float pow_body(int b, char* smem) {
    const float* Cb = g_cov + (size_t)b * D * D;
    float* v = (float*)smem;
    float* red = v + D;
    const int t = threadIdx.x;
    v[t] = 1.f;
    __syncthreads();
    float lam = 1.f;
    for (int it = 0; it < NPOW; ++it) {
        float w = 0.f;
#pragma unroll 8
        for (int j = 0; j < D; ++j) w = fmaf(Cb[(size_t)j * D + t], v[j], w);
        red[t] = w * w;
        __syncthreads();
        for (int o = 128; o > 0; o >>= 1) {
            if (t < o) red[t] += red[t + o];
            __syncthreads();
        }
        lam = sqrtf(red[0]);
        v[t] = w / fmaxf(lam, 1e-20f);
        __syncthreads();
    }
    return fmaxf(lam, 1e-12f) * 1.05f;   // inflate vs power-iter underestimate
}

__device__ void init_slice(int b, int tl, float tau) {
    const int base = b * 16384 + tl * 2048;    // float4 index
    const float invt = 1.f / tau;
    for (int i = base + (int)threadIdx.x; i < base + 2048; i += 256) {
        const int e4 = i & 16383;
        const int row = e4 >> 6;
        const int colb = (e4 & 63) << 2;
        float4 c = *(const float4*)&g_cov[(size_t)i * 4];
        float4 y0 = make_float4(c.x * invt, c.y * invt, c.z * invt, c.w * invt);
        float4 x = make_float4(c.x * (-1.f / 64.f), c.y * (-1.f / 64.f),
                               c.z * (-1.f / 64.f), c.w * (-1.f / 64.f));
        float4 e = make_float4(0.2f * x.x, 0.2f * x.y, 0.2f * x.z, 0.2f * x.w);
        const float zc = -0.5f * C1 * S1;
        float4 z1 = make_float4(zc * y0.x, zc * y0.y, zc * y0.z, zc * y0.w);
        const int dc = row - colb;
        if (dc >= 0 && dc < 4) {
            ((float*)&e)[dc] += 1.f;
            ((float*)&z1)[dc] += 1.5f * S1;
        }
        *(float4*)&g_Y[(size_t)i * 4] = y0;
        *(float4*)&g_Z[(size_t)i * 4] = x;
        *(float4*)&g_E[(size_t)i * 4] = e;
        *(float4*)&g_Zm[(size_t)i * 4] = z1;
    }
}

__device__ void frob_body(int b, char* smem) {
    float* sm = (float*)smem;
    const float* Ab = g_T + (size_t)b * D * D;
    float ss = 0.f;
    for (int i = threadIdx.x; i < D * D; i += 256) {
        float v = Ab[i];
        ss += v * v;
    }
    sm[threadIdx.x] = ss;
    __syncthreads();
    for (int o = 128; o > 0; o >>= 1) {
        if (threadIdx.x < o) sm[threadIdx.x] += sm[threadIdx.x + o];
        __syncthreads();
    }
    if (threadIdx.x == 0) g_nrm[b] = fmaxf(sqrtf(sm[0]), 1e-12f);
    __syncthreads();
}

// ---------------- chain op schedule -----------------------------------------
__device__ __forceinline__ OpDesc mkq(const float* A, const float* B, float* C,
                                      float alpha, float beta, float gamma,
                                      const float* aDev) {
    OpDesc o;
    o.A = A; o.B = B; o.C = C; o.aux = nullptr; o.alphaDev = aDev;
    o.sA = o.sB = o.sC = 65536LL;
    o.alpha = alpha; o.beta = beta; o.gamma = gamma;
    o.K = D; o.lda = D; o.ldb = D; o.ldc = D; o.Ndim = D; o.flags = 0;
    return o;
}

__device__ int chain_ops(int r, OpDesc* ops) {
    switch (r) {
    case 3:  ops[0] = mkq(g_Y,  g_Y,  g_Y2, -0.5f * C1 * S1, 1.5f * S1, 0.f, nullptr);
             ops[1] = mkq(g_Z,  g_E,  g_E2, 0.25f, 0.f, 1.f, nullptr);          return 2;
    case 4:  ops[0] = mkq(g_Zm, g_Y2, g_T,  -0.5f * C2, 0.f, 1.5f, nullptr);
             ops[1] = mkq(g_Z,  g_E2, g_E,  1.f / 3.f, 0.f, 1.f, nullptr);      return 2;
    case 5:  ops[0] = mkq(g_Y2, g_T,  g_Y,  S2, 0.f, 0.f, nullptr);
             ops[1] = mkq(g_T,  g_Zm, g_Z2, S2, 0.f, 0.f, nullptr);
             ops[2] = mkq(g_Z,  g_E,  g_E2, 0.5f, 0.f, 1.f, nullptr);           return 3;
    case 6:  ops[0] = mkq(g_Z2, g_Y,  g_T,  -0.5f * C3, 0.f, 1.5f, nullptr);
             ops[1] = mkq(g_Z,  g_E2, g_E,  1.f, 0.f, 1.f, nullptr);            return 2;
    case 7:  ops[0] = mkq(g_Y,  g_T,  g_Y2, S3, 0.f, 0.f, nullptr);
             ops[1] = mkq(g_T,  g_Z2, g_Zm, S3, 0.f, 0.f, nullptr);
             ops[2] = mkq(g_E,  g_E,  g_E2, 1.f, 0.f, 0.f, nullptr);            return 3;
    case 8:  ops[0] = mkq(g_Zm, g_Y2, g_T,  -0.5f * C4, 0.f, 1.5f, nullptr);
             ops[1] = mkq(g_E2, g_E2, g_E,  1.f, 0.f, 0.f, nullptr);            return 2;
    case 9:  ops[0] = mkq(g_Y2, g_T,  g_Y,  S4, 0.f, 0.f, nullptr);
             ops[1] = mkq(g_T,  g_Zm, g_Z2, S4, 0.f, 0.f, nullptr);
             ops[2] = mkq(g_E,  g_E,  g_E2, 1.f, 0.f, 0.f, nullptr);            return 3;
    case 10: ops[0] = mkq(g_Z2, g_Y,  g_T,  -0.5f * C5, 0.f, 1.5f, nullptr);
             ops[1] = mkq(g_E2, g_E2, g_E,  1.f, 0.f, 0.f, nullptr);            return 2;
    case 11: ops[0] = mkq(g_Y,  g_T,  g_Y2, S5, 0.f, 0.f, nullptr);
             ops[1] = mkq(g_T,  g_Z2, g_Zm, S5, 0.f, 0.f, nullptr);
             ops[2] = mkq(g_E,  g_E,  g_E2, 1.f, 0.f, 0.f, nullptr);            return 3;
    case 12: ops[0] = mkq(g_Zm, g_Y2, g_T,  -0.5f * C6, 0.f, 1.5f, nullptr);
             ops[1] = mkq(g_E2, g_E2, g_E,  1.f, 0.f, 0.f, nullptr);            return 2;
    case 13: ops[0] = mkq(g_Y2, g_T,  g_Y,  S6, 0.f, 0.f, g_stau);              return 1;
    default: ops[0] = mkq(g_Y,  g_E,  g_T,  1.f, 0.f, 0.f, nullptr);            return 1; // r14: P
    }
}

// ---------------- per-batch barrier (8 CTAs, co-resident) -------------------
__device__ __forceinline__ void batch_barrier(int b, int cnt) {
    __syncthreads();
    if (threadIdx.x == 0) {
        __threadfence();
        atomicAdd(&g_barb[b], 1u);
        const unsigned target = (unsigned)cnt * 8u;
        while (*(volatile unsigned*)&g_barb[b] < target) __nanosleep(32);
        __threadfence();
    }
    __syncthreads();
}

// ---------------- persistent per-batch chain kernel -------------------------
__global__ void __launch_bounds__(256, 2) chain_kernel(float* __restrict__ out) {
    extern __shared__ char smem[];
    const int cta = blockIdx.x;          // 0..255
    const int b   = cta >> 3;
    const int tl  = cta & 7;
    const int m0  = (tl >> 2) * 128;
    const int n0  = (tl & 3) * 64;
    int bc = 0;

    // r0: covariance (fp16, K=784): cov = Zh Zh^T / M - rmean rmean^T
    {
        OpDesc o;
        o.A = (const float*)g_Zh; o.B = (const float*)g_Zh; o.C = g_cov;
        o.aux = g_rmean; o.alphaDev = nullptr;
        o.sA = (long long)D * M; o.sB = (long long)D * M; o.sC = 65536LL;
        o.alpha = 1.f; o.beta = 0.f; o.gamma = 0.f;
        o.K = M; o.lda = M; o.ldb = M; o.ldc = D; o.Ndim = D; o.flags = 8 | 4;
        gemm_tile(o, b, m0, n0, smem);
    }
    batch_barrier(b, ++bc);

    // power iteration (redundant across the 8 CTAs; bitwise identical)
    const float tau = pow_body(b, smem);
    if (tl == 0 && threadIdx.x == 0) g_stau[b] = sqrtf(tau);
    // init slice: Y0, X, E0, Z1
    init_slice(b, tl, tau);
    batch_barrier(b, ++bc);

    // GEMM rounds (scaled NS + expm riders)
    for (int r = 3; r <= 14; ++r) {
        OpDesc ops[3];
        const int n = chain_ops(r, ops);
        for (int i = 0; i < n; ++i)
            gemm_tile(ops[i], b, m0, n0, smem);
        batch_barrier(b, ++bc);
    }

    // frob of P (tl 0 only), then all 8 CTAs write triu output
    if (tl == 0) frob_body(b, smem);
    batch_barrier(b, ++bc);

    const float sc = 1.f + g_nrm[b];
    const float* Sqb = g_Y + (size_t)b * D * D;
    float* ob = out + (size_t)b * (D * (D + 1) / 2);
    for (int i = tl * 32; i < tl * 32 + 32; ++i) {
        const size_t rowoff = (size_t)i * D - (size_t)i * (i - 1) / 2 - i;
        const float* row = Sqb + (size_t)i * D;
        for (int j = i + (int)threadIdx.x; j < D; j += 256)
            ob[rowoff + j] = sc * row[j];
    }
}

// ---------------- small kernels ---------------------------------------------
__global__ void zero_stats() {
    g_bnsum[threadIdx.x] = 0.f;
    g_bnsq[threadIdx.x] = 0.f;
    if (threadIdx.x < BATCH) g_barb[threadIdx.x] = 0u;
}

__global__ void bn_apply(const float* __restrict__ Z,
                         const float* __restrict__ gamma, const float* __restrict__ beta,
                         __half* __restrict__ Zh, float* __restrict__ rmean) {
    const int bd = blockIdx.x;
    const int d = bd & (D - 1);
    const float Ninv = 1.f / (float)(BATCH * M);
    const float mu = g_bnsum[d] * Ninv;
    const float var = g_bnsq[d] * Ninv - mu * mu;
    const float sc = rsqrtf(var + 1e-5f) * gamma[d];
    const float sh = beta[d] - mu * sc;
    const float* row = Z + (size_t)bd * M;
    __half* oh = Zh + (size_t)bd * M;
    float s = 0.f;
    for (int i = threadIdx.x; i < M; i += blockDim.x) {
        float v = fmaxf(row[i] * sc + sh, 0.f);
        oh[i] = __float2half(v);
        s += v;
    }
    __shared__ float sm[128];
    sm[threadIdx.x] = s;
    __syncthreads();
    for (int o = 64; o > 0; o >>= 1) {
        if (threadIdx.x < o) sm[threadIdx.x] += sm[threadIdx.x + o];
        __syncthreads();
    }
    if (threadIdx.x == 0) rmean[bd] = sm[0] * (1.f / (float)M);
}

// ---------------------------------------------------------------------------
static float* sym_addr(const void* symbol) {
    void* p = nullptr;
    cudaGetSymbolAddress(&p, symbol);
    return (float*)p;
}

extern "C" void kernel_launch(void* const* d_in, const int* in_sizes, int n_in,
                              void* d_out, int out_size) {
    const float* x  = (const float*)d_in[0];
    const float* w  = (const float*)d_in[1];
    const float* gm = (const float*)d_in[2];
    const float* bt = (const float*)d_in[3];
    float* out = (float*)d_out;

    float* Z   = sym_addr(g_Z);
    float* Zh  = sym_addr(g_Zh);
    float* rmn = sym_addr(g_rmean);

    cudaFuncSetAttribute(tc_conv, cudaFuncAttributeMaxDynamicSharedMemorySize, SMEM_BYTES);
    cudaFuncSetAttribute(chain_kernel, cudaFuncAttributeMaxDynamicSharedMemorySize, SMEM_BYTES);

    // 0. zero BN stats + per-batch barrier counters
    zero_stats<<<1, D>>>();
    // 1. conv 1x1 (fp16 single-MMA, trans-B, BN-stat accumulation)
    {
        OpDesc c;
        c.A = w; c.B = x; c.C = Z; c.aux = nullptr; c.alphaDev = nullptr;
        c.sA = 0LL; c.sB = (long long)CIN * M; c.sC = (long long)D * M;
        c.alpha = 1.f; c.beta = 0.f; c.gamma = 0.f;
        c.K = CIN; c.lda = CIN; c.ldb = M; c.ldc = M; c.Ndim = M; c.flags = 1 | 8 | 16;
        tc_conv<<<dim3(13, 2, 32), 256, SMEM_BYTES>>>(c);
    }
    // 2. BN apply + ReLU -> fp16 Zh + row means
    bn_apply<<<BATCH * D, 128>>>(Z, gm, bt, (__half*)Zh, rmn);
    // 3. per-batch persistent chain: cov -> pow -> init -> scaled NS + expm -> P -> frob -> triu
    chain_kernel<<<256, 256, SMEM_BYTES>>>(out);

    (void)in_sizes; (void)n_in; (void)out_size;
}